// round 1
// baseline (speedup 1.0000x reference)
#include <cuda_runtime.h>

#define Bz 128
#define Pz 37
#define Fz 2048
#define Ez 1024
#define Dz 1024
#define Az 1024
#define Vz 10000
#define Lz 20
#define Tz 19

// ---------------- scratch (static device memory; no runtime allocation) ----------------
__device__ float g_fs[17170432];
__device__ int   g_is[4096];

#define OF_IF     0
#define OF_ATT1   9699328
#define OF_IMGFC  14548992
#define OF_H1     14811136
#define OF_C1     14942208
#define OF_H2     15073280
#define OF_C2     15204352
#define OF_H1N    15335424
#define OF_H2N    15466496
#define OF_X1     15597568
#define OF_GATES  16121856
#define OF_PROJ   16646144
#define OF_AWE    16777216
#define OF_HID    17039360

#define OI_SORT   0
#define OI_DECLEN 128
#define OI_CAPS   256

// ---------------- sort (stable argsort of -lengths) + gather ints ----------------
__global__ void sort_kernel(const int* __restrict__ caplen, const int* __restrict__ enc,
                            int* __restrict__ sortp, int* __restrict__ declenp,
                            int* __restrict__ capsp,
                            float* __restrict__ o_caps, float* __restrict__ o_dlen,
                            float* __restrict__ o_sort)
{
    __shared__ int len[Bz];
    int i = threadIdx.x;
    len[i] = caplen[i];
    __syncthreads();
    int li = len[i];
    int rank = 0;
    for (int j = 0; j < Bz; j++) {
        int lj = len[j];
        rank += (lj > li) || (lj == li && j < i);
    }
    sortp[rank] = i;
    __syncthreads();
    int src = sortp[i];
    int dl = len[src] - 1;
    declenp[i] = dl;
    o_dlen[i] = (float)dl;
    o_sort[i] = (float)src;
    for (int k = 0; k < Lz; k++) {
        int c = enc[src * Lz + k];
        capsp[i * Lz + k] = c;
        o_caps[i * Lz + k] = (float)c;
    }
}

// ---------------- gather image features (concat img_att, img_fc)[sort] ----------------
__global__ void gather_kernel(const float* __restrict__ img_att, const float* __restrict__ img_fc,
                              const int* __restrict__ sortp,
                              float* __restrict__ IF, float* __restrict__ imgfc)
{
    int bp = blockIdx.x;           // 0 .. 128*37-1
    int b = bp / Pz, p = bp % Pz;
    int src = sortp[b];
    const float* s = (p < 36) ? (img_att + ((size_t)src * 36 + p) * Fz)
                              : (img_fc + (size_t)src * Fz);
    float* d = IF + (size_t)bp * Fz;
    for (int f = threadIdx.x; f < Fz; f += blockDim.x) d[f] = s[f];
    if (p == 36) {
        float* d2 = imgfc + (size_t)b * Fz;
        for (int f = threadIdx.x; f < Fz; f += blockDim.x) d2[f] = s[f];
    }
}

__global__ void zero_states(float* __restrict__ h1, float* __restrict__ c1,
                            float* __restrict__ h2, float* __restrict__ c2)
{
    int i = blockIdx.x * blockDim.x + threadIdx.x;
    if (i < Bz * Dz) { h1[i] = 0.f; c1[i] = 0.f; h2[i] = 0.f; c2[i] = 0.f; }
}

// ---------------- generic C = b1 (+b2) + A1@W1^T (+ A2@W2^T), optional relu/mask ----------------
// 64x64 tile, 128 threads, 8x4 register blocking. K1,K2 multiples of 16. M multiple of 64.
__global__ void __launch_bounds__(128)
gemm_kernel(const float* __restrict__ A1, const float* __restrict__ W1, int K1,
            const float* __restrict__ A2, const float* __restrict__ W2, int K2,
            const float* __restrict__ bias1, const float* __restrict__ bias2,
            float* __restrict__ C, int ldc, int N,
            const int* __restrict__ declen, int t, int relu)
{
    __shared__ float As[16][64];
    __shared__ float Bs[16][64];
    const int tid = threadIdx.x;
    const int n0 = blockIdx.x * 64;
    const int m0 = blockIdx.y * 64;
    const int lr = tid >> 2;          // 0..31
    const int lc = (tid & 3) << 2;    // 0,4,8,12
    const int tx = tid & 15;
    const int ty = tid >> 4;
    float acc[8][4];
#pragma unroll
    for (int i = 0; i < 8; i++)
#pragma unroll
        for (int j = 0; j < 4; j++) acc[i][j] = 0.f;

    for (int pass = 0; pass < 2; pass++) {
        const float* A = pass ? A2 : A1;
        const float* W = pass ? W2 : W1;
        const int K = pass ? K2 : K1;
        if (K == 0) continue;
        for (int k0 = 0; k0 < K; k0 += 16) {
            const float* Ap = A + (size_t)(m0 + lr) * K + k0 + lc;
            float4 a0 = *(const float4*)Ap;
            float4 a1 = *(const float4*)(Ap + (size_t)32 * K);
            float4 b0 = make_float4(0.f, 0.f, 0.f, 0.f), b1 = b0;
            if (n0 + lr < N)      b0 = *(const float4*)(W + (size_t)(n0 + lr) * K + k0 + lc);
            if (n0 + lr + 32 < N) b1 = *(const float4*)(W + (size_t)(n0 + lr + 32) * K + k0 + lc);
            __syncthreads();
            As[lc + 0][lr] = a0.x; As[lc + 1][lr] = a0.y; As[lc + 2][lr] = a0.z; As[lc + 3][lr] = a0.w;
            As[lc + 0][lr + 32] = a1.x; As[lc + 1][lr + 32] = a1.y; As[lc + 2][lr + 32] = a1.z; As[lc + 3][lr + 32] = a1.w;
            Bs[lc + 0][lr] = b0.x; Bs[lc + 1][lr] = b0.y; Bs[lc + 2][lr] = b0.z; Bs[lc + 3][lr] = b0.w;
            Bs[lc + 0][lr + 32] = b1.x; Bs[lc + 1][lr + 32] = b1.y; Bs[lc + 2][lr + 32] = b1.z; Bs[lc + 3][lr + 32] = b1.w;
            __syncthreads();
#pragma unroll
            for (int kk = 0; kk < 16; kk++) {
                float av[8], bv[4];
#pragma unroll
                for (int i = 0; i < 8; i++) av[i] = As[kk][ty * 8 + i];
#pragma unroll
                for (int j = 0; j < 4; j++) bv[j] = Bs[kk][tx * 4 + j];
#pragma unroll
                for (int i = 0; i < 8; i++)
#pragma unroll
                    for (int j = 0; j < 4; j++)
                        acc[i][j] = fmaf(av[i], bv[j], acc[i][j]);
            }
        }
    }
#pragma unroll
    for (int i = 0; i < 8; i++) {
        int m = m0 + ty * 8 + i;
        bool act = true;
        if (declen) act = (t < declen[m]);
#pragma unroll
        for (int j = 0; j < 4; j++) {
            int n = n0 + tx * 4 + j;
            if (n < N) {
                float v = acc[i][j];
                if (bias1) v += bias1[n];
                if (bias2) v += bias2[n];
                if (relu) v = fmaxf(v, 0.f);
                C[(size_t)m * ldc + n] = act ? v : 0.f;
            }
        }
    }
}

// ---------------- x1 = [emb_t, h2, image_fc] ----------------
__global__ void build_x1(const float* __restrict__ emb, const int* __restrict__ caps,
                         const float* __restrict__ h2, const float* __restrict__ imgfc,
                         float* __restrict__ x1, int t)
{
    int idx = blockIdx.x * blockDim.x + threadIdx.x;
    if (idx >= Bz * 4096) return;
    int b = idx >> 12, j = idx & 4095;
    float v;
    if (j < 1024)       v = emb[(size_t)caps[b * Lz + t] * Ez + j];
    else if (j < 2048)  v = h2[b * 1024 + j - 1024];
    else                v = imgfc[b * 2048 + j - 2048];
    x1[idx] = v;
}

// ---------------- LSTM cell elementwise; writes unmasked hn, masked-updates h,c ----------------
__global__ void lstm_kernel(const float* __restrict__ gates, float* __restrict__ h,
                            float* __restrict__ c, float* __restrict__ hn,
                            const int* __restrict__ declen, int t)
{
    int idx = blockIdx.x * blockDim.x + threadIdx.x;
    if (idx >= Bz * Dz) return;
    int b = idx >> 10, d = idx & 1023;
    const float* g = gates + (size_t)b * 4096;
    float gi = g[d], gf = g[d + 1024], gg = g[d + 2048], go = g[d + 3072];
    float si = 1.f / (1.f + expf(-gi));
    float sf = 1.f / (1.f + expf(-gf));
    float so = 1.f / (1.f + expf(-go));
    float cn = sf * c[idx] + si * tanhf(gg);
    float hv = so * tanhf(cn);
    hn[idx] = hv;
    if (t < declen[b]) { h[idx] = hv; c[idx] = cn; }
}

// ---------------- attention: scores -> softmax -> alpha out + awe ----------------
__global__ void __launch_bounds__(256)
attention_kernel(const float* __restrict__ att1, const float* __restrict__ proj,
                 const float* __restrict__ Wfull, const float* __restrict__ IF,
                 float* __restrict__ awe, float* __restrict__ o_alpha,
                 const int* __restrict__ declen, int t)
{
    int b = blockIdx.x;
    int tid = threadIdx.x;
    __shared__ float sW[1024], sP[1024], sScore[Pz], sAlpha[Pz], red[8];
    for (int a = tid; a < 1024; a += 256) { sW[a] = Wfull[a]; sP[a] = proj[b * 1024 + a]; }
    __syncthreads();
    const float* att = att1 + (size_t)b * Pz * Az;
    for (int p = 0; p < Pz; p++) {
        float part = 0.f;
        for (int a = tid; a < 1024; a += 256) {
            float e = fmaxf(att[p * 1024 + a] + sP[a], 0.f);
            part = fmaf(e, sW[a], part);
        }
        for (int o = 16; o; o >>= 1) part += __shfl_down_sync(0xffffffffu, part, o);
        if ((tid & 31) == 0) red[tid >> 5] = part;
        __syncthreads();
        if (tid == 0) {
            float s = 0.f;
            for (int w = 0; w < 8; w++) s += red[w];
            sScore[p] = s;
        }
        __syncthreads();
    }
    if (tid == 0) {
        float mx = sScore[0];
        for (int p = 1; p < Pz; p++) mx = fmaxf(mx, sScore[p]);
        float sum = 0.f;
        for (int p = 0; p < Pz; p++) { float e = expf(sScore[p] - mx); sAlpha[p] = e; sum += e; }
        float inv = 1.f / sum;
        for (int p = 0; p < Pz; p++) sAlpha[p] *= inv;
    }
    __syncthreads();
    bool act = t < declen[b];
    if (tid < Pz) o_alpha[((size_t)b * Tz + t) * Pz + tid] = act ? sAlpha[tid] : 0.f;
    const float* ifb = IF + (size_t)b * Pz * Fz;
    for (int f = tid; f < Fz; f += 256) {
        float s = 0.f;
        for (int p = 0; p < Pz; p++) s = fmaf(sAlpha[p], ifb[p * Fz + f], s);
        awe[b * Fz + f] = s;
    }
}

// ---------------- launch ----------------
extern "C" void kernel_launch(void* const* d_in, const int* in_sizes, int n_in,
                              void* d_out, int out_size)
{
    const float* img_att = (const float*)d_in[0];
    const float* img_fc  = (const float*)d_in[1];
    const int*   enc     = (const int*)d_in[2];
    const int*   caplen  = (const int*)d_in[3];
    const float* emb     = (const float*)d_in[4];
    const float* Wfa     = (const float*)d_in[5];
    const float* bfa     = (const float*)d_in[6];
    const float* Wd1     = (const float*)d_in[7];
    const float* bd1     = (const float*)d_in[8];
    const float* Wd2     = (const float*)d_in[9];
    const float* bd2     = (const float*)d_in[10];
    const float* Wfull   = (const float*)d_in[11];
    // d_in[12] = bfull (softmax shift-invariant; unused)
    const float* Wlang   = (const float*)d_in[13];
    const float* blang   = (const float*)d_in[14];
    const float* Watt    = (const float*)d_in[15];
    const float* batt    = (const float*)d_in[16];
    const float* Wout    = (const float*)d_in[17];
    const float* bout    = (const float*)d_in[18];
    const float* Wll_ih  = (const float*)d_in[19];
    const float* Wll_hh  = (const float*)d_in[20];
    const float* bll     = (const float*)d_in[21];
    const float* Wal_ih  = (const float*)d_in[22];
    const float* Wal_hh  = (const float*)d_in[23];
    const float* bal     = (const float*)d_in[24];
    const float* Wfc     = (const float*)d_in[25];
    const float* bfc     = (const float*)d_in[26];

    void* pf; cudaGetSymbolAddress(&pf, g_fs);
    void* pi; cudaGetSymbolAddress(&pi, g_is);
    float* fs = (float*)pf;
    int*   is = (int*)pi;

    float* IF    = fs + OF_IF;
    float* att1  = fs + OF_ATT1;
    float* imgfc = fs + OF_IMGFC;
    float* h1    = fs + OF_H1;
    float* c1    = fs + OF_C1;
    float* h2    = fs + OF_H2;
    float* c2    = fs + OF_C2;
    float* h1n   = fs + OF_H1N;
    float* h2n   = fs + OF_H2N;
    float* x1    = fs + OF_X1;
    float* gates = fs + OF_GATES;
    float* proj  = fs + OF_PROJ;
    float* awe   = fs + OF_AWE;
    float* hid   = fs + OF_HID;
    int* sortp   = is + OI_SORT;
    int* declenp = is + OI_DECLEN;
    int* capsp   = is + OI_CAPS;

    float* out     = (float*)d_out;
    float* o_pred  = out;
    float* o_pred1 = o_pred + (size_t)Bz * Tz * Vz;
    float* o_caps  = o_pred1 + (size_t)Bz * Tz * Vz;
    float* o_dlen  = o_caps + Bz * Lz;
    float* o_alpha = o_dlen + Bz;
    float* o_sort  = o_alpha + (size_t)Bz * Tz * Pz;

    sort_kernel<<<1, 128>>>(caplen, enc, sortp, declenp, capsp, o_caps, o_dlen, o_sort);
    gather_kernel<<<Bz * Pz, 256>>>(img_att, img_fc, sortp, IF, imgfc);
    zero_states<<<(Bz * Dz + 255) / 256, 256>>>(h1, c1, h2, c2);

    // att1 = IF @ Wfa^T + bfa : M=4736, N=1024, K=2048
    gemm_kernel<<<dim3(16, 74), 128>>>(IF, Wfa, 2048, nullptr, nullptr, 0,
                                       bfa, nullptr, att1, 1024, 1024, nullptr, 0, 0);

    for (int t = 0; t < Tz; t++) {
        build_x1<<<(Bz * 4096 + 255) / 256, 256>>>(emb, capsp, h2, imgfc, x1, t);
        // gates1 = x1@Wll_ih^T + h1@Wll_hh^T + bll
        gemm_kernel<<<dim3(64, 2), 128>>>(x1, Wll_ih, 4096, h1, Wll_hh, 1024,
                                          bll, nullptr, gates, 4096, 4096, nullptr, 0, 0);
        lstm_kernel<<<(Bz * Dz + 255) / 256, 256>>>(gates, h1, c1, h1n, declenp, t);
        // preds1 = h1n@Wfc^T + bfc (masked) -> o_pred1[:, t, :]
        gemm_kernel<<<dim3(157, 2), 128>>>(h1n, Wfc, 1024, nullptr, nullptr, 0,
                                           bfc, nullptr, o_pred1 + (size_t)t * Vz,
                                           Tz * Vz, Vz, declenp, t, 0);
        // proj = h1n@Wd1^T + bd1 + h2@Wd2^T + bd2
        gemm_kernel<<<dim3(16, 2), 128>>>(h1n, Wd1, 1024, h2, Wd2, 1024,
                                          bd1, bd2, proj, 1024, 1024, nullptr, 0, 0);
        attention_kernel<<<Bz, 256>>>(att1, proj, Wfull, IF, awe, o_alpha, declenp, t);
        // gates2 = awe@Wal_ih^T + h2@Wal_hh^T + bal
        gemm_kernel<<<dim3(64, 2), 128>>>(awe, Wal_ih, 2048, h2, Wal_hh, 1024,
                                          bal, nullptr, gates, 4096, 4096, nullptr, 0, 0);
        lstm_kernel<<<(Bz * Dz + 255) / 256, 256>>>(gates, h2, c2, h2n, declenp, t);
        // hid = relu([h1n@Wlang^T + blang, h2n@Watt^T + batt])
        gemm_kernel<<<dim3(8, 2), 128>>>(h1n, Wlang, 1024, nullptr, nullptr, 0,
                                         blang, nullptr, hid, 1024, 512, nullptr, 0, 1);
        gemm_kernel<<<dim3(8, 2), 128>>>(h2n, Watt, 1024, nullptr, nullptr, 0,
                                         batt, nullptr, hid + 512, 1024, 512, nullptr, 0, 1);
        // out = hid@Wout^T + bout (masked) -> o_pred[:, t, :]
        gemm_kernel<<<dim3(157, 2), 128>>>(hid, Wout, 1024, nullptr, nullptr, 0,
                                           bout, nullptr, o_pred + (size_t)t * Vz,
                                           Tz * Vz, Vz, declenp, t, 0);
    }
}

// round 2
// speedup vs baseline: 1.0011x; 1.0011x over previous
#include <cuda_runtime.h>

#define Bz 128
#define Pz 37
#define Fz 2048
#define Ez 1024
#define Dz 1024
#define Az 1024
#define Vz 10000
#define Lz 20
#define Tz 19

// ---------------- scratch (static device memory; no runtime allocation) ----------------
__device__ float g_fs[17170432];
__device__ int   g_is[4096];

#define OF_IF     0
#define OF_ATT1   9699328
#define OF_IMGFC  14548992
#define OF_H1     14811136
#define OF_C1     14942208
#define OF_H2     15073280
#define OF_C2     15204352
#define OF_H1N    15335424
#define OF_H2N    15466496
#define OF_X1     15597568
#define OF_GATES  16121856
#define OF_PROJ   16646144
#define OF_AWE    16777216
#define OF_HID    17039360

#define OI_SORT   0
#define OI_DECLEN 128
#define OI_CAPS   256

// ---------------- sort (stable argsort of -lengths) + gather ints ----------------
__global__ void sort_kernel(const int* __restrict__ caplen, const int* __restrict__ enc,
                            int* __restrict__ sortp, int* __restrict__ declenp,
                            int* __restrict__ capsp,
                            float* __restrict__ o_caps, float* __restrict__ o_dlen,
                            float* __restrict__ o_sort)
{
    __shared__ int len[Bz];
    int i = threadIdx.x;
    len[i] = caplen[i];
    __syncthreads();
    int li = len[i];
    int rank = 0;
    for (int j = 0; j < Bz; j++) {
        int lj = len[j];
        rank += (lj > li) || (lj == li && j < i);
    }
    sortp[rank] = i;
    __syncthreads();
    int src = sortp[i];
    int dl = len[src] - 1;
    declenp[i] = dl;
    o_dlen[i] = (float)dl;
    o_sort[i] = (float)src;
    for (int k = 0; k < Lz; k++) {
        int c = enc[src * Lz + k];
        capsp[i * Lz + k] = c;
        o_caps[i * Lz + k] = (float)c;
    }
}

// ---------------- gather image features (concat img_att, img_fc)[sort] ----------------
__global__ void gather_kernel(const float* __restrict__ img_att, const float* __restrict__ img_fc,
                              const int* __restrict__ sortp,
                              float* __restrict__ IF, float* __restrict__ imgfc)
{
    int bp = blockIdx.x;           // 0 .. 128*37-1
    int b = bp / Pz, p = bp % Pz;
    int src = sortp[b];
    const float* s = (p < 36) ? (img_att + ((size_t)src * 36 + p) * Fz)
                              : (img_fc + (size_t)src * Fz);
    float* d = IF + (size_t)bp * Fz;
    for (int f = threadIdx.x; f < Fz; f += blockDim.x) d[f] = s[f];
    if (p == 36) {
        float* d2 = imgfc + (size_t)b * Fz;
        for (int f = threadIdx.x; f < Fz; f += blockDim.x) d2[f] = s[f];
    }
}

__global__ void zero_states(float* __restrict__ h1, float* __restrict__ c1,
                            float* __restrict__ h2, float* __restrict__ c2)
{
    int i = blockIdx.x * blockDim.x + threadIdx.x;
    if (i < Bz * Dz) { h1[i] = 0.f; c1[i] = 0.f; h2[i] = 0.f; c2[i] = 0.f; }
}

// ---------------- generic C = b1 (+b2) + A1@W1^T (+ A2@W2^T), optional relu/mask ----------------
// 64x64 tile, 128 threads, 8x4 register blocking. K1,K2 multiples of 16. M multiple of 64.
__global__ void __launch_bounds__(128)
gemm_kernel(const float* __restrict__ A1, const float* __restrict__ W1, int K1,
            const float* __restrict__ A2, const float* __restrict__ W2, int K2,
            const float* __restrict__ bias1, const float* __restrict__ bias2,
            float* __restrict__ C, int ldc, int N,
            const int* __restrict__ declen, int t, int relu)
{
    __shared__ float As[16][64];
    __shared__ float Bs[16][64];
    const int tid = threadIdx.x;
    const int n0 = blockIdx.x * 64;
    const int m0 = blockIdx.y * 64;
    const int lr = tid >> 2;          // 0..31
    const int lc = (tid & 3) << 2;    // 0,4,8,12
    const int tx = tid & 15;
    const int ty = tid >> 4;
    float acc[8][4];
#pragma unroll
    for (int i = 0; i < 8; i++)
#pragma unroll
        for (int j = 0; j < 4; j++) acc[i][j] = 0.f;

    for (int pass = 0; pass < 2; pass++) {
        const float* A = pass ? A2 : A1;
        const float* W = pass ? W2 : W1;
        const int K = pass ? K2 : K1;
        if (K == 0) continue;
        for (int k0 = 0; k0 < K; k0 += 16) {
            const float* Ap = A + (size_t)(m0 + lr) * K + k0 + lc;
            float4 a0 = *(const float4*)Ap;
            float4 a1 = *(const float4*)(Ap + (size_t)32 * K);
            float4 b0 = make_float4(0.f, 0.f, 0.f, 0.f), b1 = b0;
            if (n0 + lr < N)      b0 = *(const float4*)(W + (size_t)(n0 + lr) * K + k0 + lc);
            if (n0 + lr + 32 < N) b1 = *(const float4*)(W + (size_t)(n0 + lr + 32) * K + k0 + lc);
            __syncthreads();
            As[lc + 0][lr] = a0.x; As[lc + 1][lr] = a0.y; As[lc + 2][lr] = a0.z; As[lc + 3][lr] = a0.w;
            As[lc + 0][lr + 32] = a1.x; As[lc + 1][lr + 32] = a1.y; As[lc + 2][lr + 32] = a1.z; As[lc + 3][lr + 32] = a1.w;
            Bs[lc + 0][lr] = b0.x; Bs[lc + 1][lr] = b0.y; Bs[lc + 2][lr] = b0.z; Bs[lc + 3][lr] = b0.w;
            Bs[lc + 0][lr + 32] = b1.x; Bs[lc + 1][lr + 32] = b1.y; Bs[lc + 2][lr + 32] = b1.z; Bs[lc + 3][lr + 32] = b1.w;
            __syncthreads();
#pragma unroll
            for (int kk = 0; kk < 16; kk++) {
                float av[8], bv[4];
#pragma unroll
                for (int i = 0; i < 8; i++) av[i] = As[kk][ty * 8 + i];
#pragma unroll
                for (int j = 0; j < 4; j++) bv[j] = Bs[kk][tx * 4 + j];
#pragma unroll
                for (int i = 0; i < 8; i++)
#pragma unroll
                    for (int j = 0; j < 4; j++)
                        acc[i][j] = fmaf(av[i], bv[j], acc[i][j]);
            }
        }
    }
#pragma unroll
    for (int i = 0; i < 8; i++) {
        int m = m0 + ty * 8 + i;
        bool act = true;
        if (declen) act = (t < declen[m]);
#pragma unroll
        for (int j = 0; j < 4; j++) {
            int n = n0 + tx * 4 + j;
            if (n < N) {
                float v = acc[i][j];
                if (bias1) v += bias1[n];
                if (bias2) v += bias2[n];
                if (relu) v = fmaxf(v, 0.f);
                C[(size_t)m * ldc + n] = act ? v : 0.f;
            }
        }
    }
}

// ---------------- x1 = [emb_t, h2, image_fc] ----------------
__global__ void build_x1(const float* __restrict__ emb, const int* __restrict__ caps,
                         const float* __restrict__ h2, const float* __restrict__ imgfc,
                         float* __restrict__ x1, int t)
{
    int idx = blockIdx.x * blockDim.x + threadIdx.x;
    if (idx >= Bz * 4096) return;
    int b = idx >> 12, j = idx & 4095;
    float v;
    if (j < 1024)       v = emb[(size_t)caps[b * Lz + t] * Ez + j];
    else if (j < 2048)  v = h2[b * 1024 + j - 1024];
    else                v = imgfc[b * 2048 + j - 2048];
    x1[idx] = v;
}

// ---------------- LSTM cell elementwise; writes unmasked hn, masked-updates h,c ----------------
__global__ void lstm_kernel(const float* __restrict__ gates, float* __restrict__ h,
                            float* __restrict__ c, float* __restrict__ hn,
                            const int* __restrict__ declen, int t)
{
    int idx = blockIdx.x * blockDim.x + threadIdx.x;
    if (idx >= Bz * Dz) return;
    int b = idx >> 10, d = idx & 1023;
    const float* g = gates + (size_t)b * 4096;
    float gi = g[d], gf = g[d + 1024], gg = g[d + 2048], go = g[d + 3072];
    float si = 1.f / (1.f + expf(-gi));
    float sf = 1.f / (1.f + expf(-gf));
    float so = 1.f / (1.f + expf(-go));
    float cn = sf * c[idx] + si * tanhf(gg);
    float hv = so * tanhf(cn);
    hn[idx] = hv;
    if (t < declen[b]) { h[idx] = hv; c[idx] = cn; }
}

// ---------------- attention: scores -> softmax -> alpha out + awe ----------------
__global__ void __launch_bounds__(256)
attention_kernel(const float* __restrict__ att1, const float* __restrict__ proj,
                 const float* __restrict__ Wfull, const float* __restrict__ IF,
                 float* __restrict__ awe, float* __restrict__ o_alpha,
                 const int* __restrict__ declen, int t)
{
    int b = blockIdx.x;
    int tid = threadIdx.x;
    __shared__ float sW[1024], sP[1024], sScore[Pz], sAlpha[Pz], red[8];
    for (int a = tid; a < 1024; a += 256) { sW[a] = Wfull[a]; sP[a] = proj[b * 1024 + a]; }
    __syncthreads();
    const float* att = att1 + (size_t)b * Pz * Az;
    for (int p = 0; p < Pz; p++) {
        float part = 0.f;
        for (int a = tid; a < 1024; a += 256) {
            float e = fmaxf(att[p * 1024 + a] + sP[a], 0.f);
            part = fmaf(e, sW[a], part);
        }
        for (int o = 16; o; o >>= 1) part += __shfl_down_sync(0xffffffffu, part, o);
        if ((tid & 31) == 0) red[tid >> 5] = part;
        __syncthreads();
        if (tid == 0) {
            float s = 0.f;
            for (int w = 0; w < 8; w++) s += red[w];
            sScore[p] = s;
        }
        __syncthreads();
    }
    if (tid == 0) {
        float mx = sScore[0];
        for (int p = 1; p < Pz; p++) mx = fmaxf(mx, sScore[p]);
        float sum = 0.f;
        for (int p = 0; p < Pz; p++) { float e = expf(sScore[p] - mx); sAlpha[p] = e; sum += e; }
        float inv = 1.f / sum;
        for (int p = 0; p < Pz; p++) sAlpha[p] *= inv;
    }
    __syncthreads();
    bool act = t < declen[b];
    if (tid < Pz) o_alpha[((size_t)b * Tz + t) * Pz + tid] = act ? sAlpha[tid] : 0.f;
    const float* ifb = IF + (size_t)b * Pz * Fz;
    for (int f = tid; f < Fz; f += 256) {
        float s = 0.f;
        for (int p = 0; p < Pz; p++) s = fmaf(sAlpha[p], ifb[p * Fz + f], s);
        awe[b * Fz + f] = s;
    }
}

// ---------------- launch ----------------
extern "C" void kernel_launch(void* const* d_in, const int* in_sizes, int n_in,
                              void* d_out, int out_size)
{
    const float* img_att = (const float*)d_in[0];
    const float* img_fc  = (const float*)d_in[1];
    const int*   enc     = (const int*)d_in[2];
    const int*   caplen  = (const int*)d_in[3];
    const float* emb     = (const float*)d_in[4];
    const float* Wfa     = (const float*)d_in[5];
    const float* bfa     = (const float*)d_in[6];
    const float* Wd1     = (const float*)d_in[7];
    const float* bd1     = (const float*)d_in[8];
    const float* Wd2     = (const float*)d_in[9];
    const float* bd2     = (const float*)d_in[10];
    const float* Wfull   = (const float*)d_in[11];
    // d_in[12] = bfull (softmax shift-invariant; unused)
    const float* Wlang   = (const float*)d_in[13];
    const float* blang   = (const float*)d_in[14];
    const float* Watt    = (const float*)d_in[15];
    const float* batt    = (const float*)d_in[16];
    const float* Wout    = (const float*)d_in[17];
    const float* bout    = (const float*)d_in[18];
    const float* Wll_ih  = (const float*)d_in[19];
    const float* Wll_hh  = (const float*)d_in[20];
    const float* bll     = (const float*)d_in[21];
    const float* Wal_ih  = (const float*)d_in[22];
    const float* Wal_hh  = (const float*)d_in[23];
    const float* bal     = (const float*)d_in[24];
    const float* Wfc     = (const float*)d_in[25];
    const float* bfc     = (const float*)d_in[26];

    void* pf; cudaGetSymbolAddress(&pf, g_fs);
    void* pi; cudaGetSymbolAddress(&pi, g_is);
    float* fs = (float*)pf;
    int*   is = (int*)pi;

    float* IF    = fs + OF_IF;
    float* att1  = fs + OF_ATT1;
    float* imgfc = fs + OF_IMGFC;
    float* h1    = fs + OF_H1;
    float* c1    = fs + OF_C1;
    float* h2    = fs + OF_H2;
    float* c2    = fs + OF_C2;
    float* h1n   = fs + OF_H1N;
    float* h2n   = fs + OF_H2N;
    float* x1    = fs + OF_X1;
    float* gates = fs + OF_GATES;
    float* proj  = fs + OF_PROJ;
    float* awe   = fs + OF_AWE;
    float* hid   = fs + OF_HID;
    int* sortp   = is + OI_SORT;
    int* declenp = is + OI_DECLEN;
    int* capsp   = is + OI_CAPS;

    float* out     = (float*)d_out;
    float* o_pred  = out;
    float* o_pred1 = o_pred + (size_t)Bz * Tz * Vz;
    float* o_caps  = o_pred1 + (size_t)Bz * Tz * Vz;
    float* o_dlen  = o_caps + Bz * Lz;
    float* o_alpha = o_dlen + Bz;
    float* o_sort  = o_alpha + (size_t)Bz * Tz * Pz;

    sort_kernel<<<1, 128>>>(caplen, enc, sortp, declenp, capsp, o_caps, o_dlen, o_sort);
    gather_kernel<<<Bz * Pz, 256>>>(img_att, img_fc, sortp, IF, imgfc);
    zero_states<<<(Bz * Dz + 255) / 256, 256>>>(h1, c1, h2, c2);

    // att1 = IF @ Wfa^T + bfa : M=4736, N=1024, K=2048
    gemm_kernel<<<dim3(16, 74), 128>>>(IF, Wfa, 2048, nullptr, nullptr, 0,
                                       bfa, nullptr, att1, 1024, 1024, nullptr, 0, 0);

    for (int t = 0; t < Tz; t++) {
        build_x1<<<(Bz * 4096 + 255) / 256, 256>>>(emb, capsp, h2, imgfc, x1, t);
        // gates1 = x1@Wll_ih^T + h1@Wll_hh^T + bll
        gemm_kernel<<<dim3(64, 2), 128>>>(x1, Wll_ih, 4096, h1, Wll_hh, 1024,
                                          bll, nullptr, gates, 4096, 4096, nullptr, 0, 0);
        lstm_kernel<<<(Bz * Dz + 255) / 256, 256>>>(gates, h1, c1, h1n, declenp, t);
        // preds1 = h1n@Wfc^T + bfc (masked) -> o_pred1[:, t, :]
        gemm_kernel<<<dim3(157, 2), 128>>>(h1n, Wfc, 1024, nullptr, nullptr, 0,
                                           bfc, nullptr, o_pred1 + (size_t)t * Vz,
                                           Tz * Vz, Vz, declenp, t, 0);
        // proj = h1n@Wd1^T + bd1 + h2@Wd2^T + bd2
        gemm_kernel<<<dim3(16, 2), 128>>>(h1n, Wd1, 1024, h2, Wd2, 1024,
                                          bd1, bd2, proj, 1024, 1024, nullptr, 0, 0);
        attention_kernel<<<Bz, 256>>>(att1, proj, Wfull, IF, awe, o_alpha, declenp, t);
        // gates2 = awe@Wal_ih^T + h2@Wal_hh^T + bal
        gemm_kernel<<<dim3(64, 2), 128>>>(awe, Wal_ih, 2048, h2, Wal_hh, 1024,
                                          bal, nullptr, gates, 4096, 4096, nullptr, 0, 0);
        lstm_kernel<<<(Bz * Dz + 255) / 256, 256>>>(gates, h2, c2, h2n, declenp, t);
        // hid = relu([h1n@Wlang^T + blang, h2n@Watt^T + batt])
        gemm_kernel<<<dim3(8, 2), 128>>>(h1n, Wlang, 1024, nullptr, nullptr, 0,
                                         blang, nullptr, hid, 1024, 512, nullptr, 0, 1);
        gemm_kernel<<<dim3(8, 2), 128>>>(h2n, Watt, 1024, nullptr, nullptr, 0,
                                         batt, nullptr, hid + 512, 1024, 512, nullptr, 0, 1);
        // out = hid@Wout^T + bout (masked) -> o_pred[:, t, :]
        gemm_kernel<<<dim3(157, 2), 128>>>(hid, Wout, 1024, nullptr, nullptr, 0,
                                           bout, nullptr, o_pred + (size_t)t * Vz,
                                           Tz * Vz, Vz, declenp, t, 0);
    }
}

// round 9
// speedup vs baseline: 4.0388x; 4.0344x over previous
#include <cuda_runtime.h>
#include <cuda_bf16.h>
#include <cstdint>

typedef __nv_bfloat16 bf;
#define Bz 128
#define Pz 37
#define Fz 2048
#define Vz 10000
#define Lz 20
#define Tz 19

#define TILEB 10240
#define BUFB  40960
#define GSM   81920

__device__ __forceinline__ uint32_t smem_u32(const void* p) {
    uint32_t a;
    asm("{ .reg .u64 t; cvta.to.shared.u64 t, %1; cvt.u32.u64 %0, t; }" : "=r"(a) : "l"(p));
    return a;
}

#define LDMX4(R, addr) \
    asm volatile("ldmatrix.sync.aligned.m8n8.x4.shared.b16 {%0,%1,%2,%3}, [%4];" \
        : "=r"((R)[0]), "=r"((R)[1]), "=r"((R)[2]), "=r"((R)[3]) : "r"(addr))

#define MMA(C, A, B) \
    asm volatile("mma.sync.aligned.m16n8k16.row.col.f32.bf16.bf16.f32 " \
        "{%0,%1,%2,%3},{%4,%5,%6,%7},{%8,%9},{%0,%1,%2,%3};" \
        : "+f"((C)[0]), "+f"((C)[1]), "+f"((C)[2]), "+f"((C)[3]) \
        : "r"((A)[0]), "r"((A)[1]), "r"((A)[2]), "r"((A)[3]), "r"((B)[0]), "r"((B)[1]))

#define CPA(d, g) \
    asm volatile("cp.async.cg.shared.global [%0], [%1], 16;" :: "r"(d), "l"(g))

// ---------- static device memory ----------
__device__ float g_fs[28313600];
__device__ bf    g_hb[146276352];
__device__ int   g_is[4096];

#define FS_IF     0
#define FS_IMGFC  9699328
#define FS_ATT1   9961472
#define FS_EALL   14811136
#define FS_GFC    24772608
#define FS_PROJ   25296896
#define FS_C1     25427968
#define FS_C2     25559040
#define FS_PROJB  25690112
#define FS_HIDB   25691136
#define FS_PART   25692160

#define HB_WFA    0
#define HB_WE     4194304
#define HB_WH     12582912
#define HB_WF     20971520
#define HB_WHH    37748736
#define HB_WALI   46137344
#define HB_WALH   62914560
#define HB_WD1    71303168
#define HB_WD2    73400320
#define HB_WLANG  75497472
#define HB_WATT   76546048
#define HB_WFCP   77594624
#define HB_WOUTP  98566144
#define HB_IF     119537664
#define HB_IMGFC  138936320
#define HB_EMBG   139460608
#define HB_H1     144441344
#define HB_H2     144703488
#define HB_H1N    144965632
#define HB_H2N    145227776
#define HB_AWE    145489920
#define HB_HID    146014208

__device__ __forceinline__ void split2(float v, bf* dh, bf* dl) {
    bf h = __float2bfloat16(v);
    *dh = h;
    *dl = __float2bfloat16(v - __bfloat162float(h));
}

// ---------- preprocessing ----------
__global__ void sort_kernel(const int* __restrict__ caplen, const int* __restrict__ enc,
                            int* sortp, int* declenp, int* capsp,
                            float* o_caps, float* o_dlen, float* o_sort)
{
    __shared__ int len[Bz];
    int i = threadIdx.x;
    len[i] = caplen[i];
    __syncthreads();
    int li = len[i], rank = 0;
    for (int j = 0; j < Bz; j++) {
        int lj = len[j];
        rank += (lj > li) || (lj == li && j < i);
    }
    sortp[rank] = i;
    __syncthreads();
    int src = sortp[i];
    int dl = len[src] - 1;
    declenp[i] = dl;
    o_dlen[i] = (float)dl;
    o_sort[i] = (float)src;
    for (int k = 0; k < Lz; k++) {
        int c = enc[src * Lz + k];
        capsp[i * Lz + k] = c;
        o_caps[i * Lz + k] = (float)c;
    }
}

__global__ void gather_kernel(const float* __restrict__ img_att, const float* __restrict__ img_fc,
                              const int* __restrict__ sortp, float* IF, float* imgfc)
{
    int bp = blockIdx.x, b = bp / Pz, p = bp % Pz;
    int src = sortp[b];
    const float* s = (p < 36) ? (img_att + ((size_t)src * 36 + p) * Fz) : (img_fc + (size_t)src * Fz);
    float* d = IF + (size_t)bp * Fz;
    for (int f = threadIdx.x; f < Fz; f += blockDim.x) d[f] = s[f];
    if (p == 36) {
        float* d2 = imgfc + (size_t)b * Fz;
        for (int f = threadIdx.x; f < Fz; f += blockDim.x) d2[f] = s[f];
    }
}

__global__ void gather_emb(const float* __restrict__ emb, const int* __restrict__ caps,
                           bf* dh, bf* dl)
{
    int r = blockIdx.x, t = r >> 7, b = r & 127;
    const float* s = emb + (size_t)caps[b * Lz + t] * 1024;
    for (int c = threadIdx.x; c < 1024; c += blockDim.x)
        split2(s[c], dh + (size_t)r * 1024 + c, dl + (size_t)r * 1024 + c);
}

__global__ void convert_split(const float* __restrict__ src, int ls, int srcR, int n, int C,
                              bf* dh, bf* dl)
{
    int i = blockIdx.x * blockDim.x + threadIdx.x;
    if (i >= n) return;
    int r = i / C, c = i % C;
    float v = (r < srcR) ? src[(size_t)r * ls + c] : 0.f;
    split2(v, dh + i, dl + i);
}

__global__ void make_bias(const float* bd1, const float* bd2, const float* blang,
                          const float* batt, float* projb, float* hidb)
{
    int i = blockIdx.x * blockDim.x + threadIdx.x;
    if (i < 1024) {
        projb[i] = bd1[i] + bd2[i];
        hidb[i] = (i < 512) ? blang[i] : batt[i - 512];
    }
}

__global__ void zero_init(float* c1, float* c2, bf* h1, bf* h2)
{
    int i = blockIdx.x * blockDim.x + threadIdx.x;
    if (i < 262144) {
        h1[i] = __float2bfloat16(0.f);
        h2[i] = __float2bfloat16(0.f);
        if (i < 131072) { c1[i] = 0.f; c2[i] = 0.f; }
    }
}

// ---------- mma.sync bf16 GEMM: partial[sb+z] = A@W^T over K-slice z ----------
// 128x128 tile, BK=32, 256 thr (8 warps 2x4, warp 64x32), hi/lo 3-term.
__global__ void __launch_bounds__(256, 1)
gemm_ms(const bf* A1h, const bf* A1l, const bf* W1h, const bf* W1l,
        int K1, int S1, int NT1, int n01, int sb1,
        const bf* A2h, const bf* A2l, const bf* W2h, const bf* W2l,
        int K2, int S2, int NT2, int n02, int sb2,
        float* __restrict__ partial, int ldP, int ss)
{
    extern __shared__ char smem[];
    const int bx = blockIdx.x;
    const bf *Ah, *Al, *Wh, *Wl;
    int K, S, n0, sb;
    if (bx < NT1) { Ah = A1h; Al = A1l; Wh = W1h; Wl = W1l; K = K1; S = S1; n0 = n01 + bx * 128; sb = sb1; }
    else          { Ah = A2h; Al = A2l; Wh = W2h; Wl = W2l; K = K2; S = S2; n0 = n02 + (bx - NT1) * 128; sb = sb2; }
    const int s = blockIdx.z;
    if (s >= S) return;
    const int m0 = blockIdx.y * 128;
    const int Ks = K / S, ks0 = s * Ks, NC = Ks / 32;

    const int tid = threadIdx.x, lane = tid & 31, warp = tid >> 5;
    const int wm = warp >> 2, wn = warp & 3;
    const uint32_t sbase = smem_u32(smem);

    // loader mapping: 4 tiles x 64 threads; each thread 8 x 16B (rows r0+16j, chunk c0)
    const int tile = tid >> 6, u0 = tid & 63;
    const int r0 = u0 >> 2, c0 = u0 & 3;
    const bf* sp = (tile == 0) ? Ah : (tile == 1) ? Al : (tile == 2) ? Wh : Wl;
    const int rb = (tile < 2) ? m0 : n0;
    const bf* gbase = sp + (size_t)(rb + r0) * K + ks0 + c0 * 8;
    const size_t K16 = (size_t)16 * K;
    const uint32_t dbase = sbase + tile * TILEB + r0 * 80 + c0 * 16;

    // ldmatrix lane addressing
    const int arow = (lane & 7) + ((lane >> 3) & 1) * 8;
    const uint32_t akoff = (uint32_t)((lane >> 4) * 16);
    const int brow = (lane & 7) + ((lane >> 4) << 3);
    const uint32_t bkoff = (uint32_t)(((lane >> 3) & 1) * 16);
    const uint32_t aoff = (uint32_t)((wm * 64 + arow) * 80) + akoff;
    const uint32_t boff = 2u * TILEB + (uint32_t)((wn * 32 + brow) * 80) + bkoff;

    float acc[4][4][4] = {};

    // prologue: chunk 0
    {
        const bf* g = gbase;
        uint32_t d = dbase;
#pragma unroll
        for (int j = 0; j < 8; j++) CPA(d + j * 1280, g + (size_t)j * K16);
        asm volatile("cp.async.commit_group;" ::: "memory");
    }
    for (int c = 0; c < NC; c++) {
        if (c + 1 < NC) {
            const bf* g = gbase + (size_t)(c + 1) * 32;
            uint32_t d = dbase + ((c + 1) & 1) * BUFB;
#pragma unroll
            for (int j = 0; j < 8; j++) CPA(d + j * 1280, g + (size_t)j * K16);
            asm volatile("cp.async.commit_group;" ::: "memory");
            asm volatile("cp.async.wait_group 1;" ::: "memory");
        } else {
            asm volatile("cp.async.wait_group 0;" ::: "memory");
        }
        __syncthreads();
        const uint32_t sc = sbase + (c & 1) * BUFB;
#pragma unroll
        for (int kk = 0; kk < 2; kk++) {
            const uint32_t kb = kk * 32;
            uint32_t Bh[8], Bl[8];
#pragma unroll
            for (int p = 0; p < 2; p++) {
                LDMX4(&Bh[4 * p], sc + boff + p * 1280 + kb);
                LDMX4(&Bl[4 * p], sc + boff + TILEB + p * 1280 + kb);
            }
#pragma unroll
            for (int mt = 0; mt < 4; mt++) {
                uint32_t Af[4], Ag[4];
                LDMX4(Af, sc + aoff + mt * 1280 + kb);
                LDMX4(Ag, sc + aoff + TILEB + mt * 1280 + kb);
#pragma unroll
                for (int nt = 0; nt < 4; nt++) {
                    MMA(acc[mt][nt], Af, &Bh[2 * nt]);
                    MMA(acc[mt][nt], Af, &Bl[2 * nt]);
                    MMA(acc[mt][nt], Ag, &Bh[2 * nt]);
                }
            }
        }
        __syncthreads();
    }
    // epilogue: fp32 partial
    float* op = partial + (size_t)(sb + s) * ss;
    const int rr = lane >> 2, cc = (lane & 3) * 2;
#pragma unroll
    for (int mt = 0; mt < 4; mt++) {
        int row = m0 + wm * 64 + mt * 16 + rr;
#pragma unroll
        for (int nt = 0; nt < 4; nt++) {
            int col = n0 + wn * 32 + nt * 8 + cc;
            *(float2*)(op + (size_t)row * ldP + col) = make_float2(acc[mt][nt][0], acc[mt][nt][1]);
            *(float2*)(op + (size_t)(row + 8) * ldP + col) = make_float2(acc[mt][nt][2], acc[mt][nt][3]);
        }
    }
}

// ---------- finish kernels ----------
__global__ void finish_linear(const float* __restrict__ P, int Z, int ss, int ldP,
                              const float* __restrict__ bias, int relu,
                              const int* __restrict__ declen, int t,
                              float* __restrict__ outF, int ldo,
                              bf* dh, bf* dl, int M, int N)
{
    int i = blockIdx.x * blockDim.x + threadIdx.x;
    if (i >= M * N) return;
    int m = i / N, n = i % N;
    float v = bias ? bias[n] : 0.f;
    const float* p = P + (size_t)m * ldP + n;
    for (int z = 0; z < Z; z++) v += p[(size_t)z * ss];
    if (relu) v = fmaxf(v, 0.f);
    if (declen && !(t < declen[m])) v = 0.f;
    if (outF) outF[(size_t)m * ldo + n] = v;
    if (dh) split2(v, dh + i, dl + i);
}

__global__ void finish_lstm(const float* __restrict__ P, int Z, int ss,
                            const float* __restrict__ addA, const float* __restrict__ addB,
                            const float* __restrict__ bias, float* __restrict__ cst,
                            bf* hh, bf* hl, bf* hnh, bf* hnl,
                            const int* __restrict__ declen, int t)
{
    int idx = blockIdx.x * blockDim.x + threadIdx.x;
    if (idx >= Bz * 1024) return;
    int b = idx >> 10, d = idx & 1023;
    float g4[4];
#pragma unroll
    for (int q = 0; q < 4; q++) {
        int n = d + q * 1024;
        float v = bias[n];
        if (addA) v += addA[b * 4096 + n];
        if (addB) v += addB[b * 4096 + n];
        for (int z = 0; z < Z; z++) v += P[(size_t)z * ss + b * 4096 + n];
        g4[q] = v;
    }
    float si = 1.f / (1.f + expf(-g4[0]));
    float sf = 1.f / (1.f + expf(-g4[1]));
    float so = 1.f / (1.f + expf(-g4[3]));
    float cn = sf * cst[idx] + si * tanhf(g4[2]);
    float hv = so * tanhf(cn);
    split2(hv, hnh + idx, hnl + idx);
    if (t < declen[b]) { cst[idx] = cn; split2(hv, hh + idx, hl + idx); }
}

// ---------- attention ----------
__global__ void __launch_bounds__(256)
attention_kernel(const float* __restrict__ att1, const float* __restrict__ proj,
                 const float* __restrict__ Wfull, const float* __restrict__ IF,
                 bf* aweh, bf* awel, float* __restrict__ o_alpha,
                 const int* __restrict__ declen, int t)
{
    int b = blockIdx.x, tid = threadIdx.x;
    __shared__ float sW[1024], sP[1024], sScore[Pz], sAlpha[Pz], red[8];
    for (int a = tid; a < 1024; a += 256) { sW[a] = Wfull[a]; sP[a] = proj[b * 1024 + a]; }
    __syncthreads();
    const float* att = att1 + (size_t)b * Pz * 1024;
    for (int p = 0; p < Pz; p++) {
        float part = 0.f;
        for (int a = tid; a < 1024; a += 256) {
            float e = fmaxf(att[p * 1024 + a] + sP[a], 0.f);
            part = fmaf(e, sW[a], part);
        }
        for (int o = 16; o; o >>= 1) part += __shfl_down_sync(0xffffffffu, part, o);
        if ((tid & 31) == 0) red[tid >> 5] = part;
        __syncthreads();
        if (tid == 0) {
            float ssum = 0.f;
            for (int w = 0; w < 8; w++) ssum += red[w];
            sScore[p] = ssum;
        }
        __syncthreads();
    }
    if (tid == 0) {
        float mx = sScore[0];
        for (int p = 1; p < Pz; p++) mx = fmaxf(mx, sScore[p]);
        float sum = 0.f;
        for (int p = 0; p < Pz; p++) { float e = expf(sScore[p] - mx); sAlpha[p] = e; sum += e; }
        float inv = 1.f / sum;
        for (int p = 0; p < Pz; p++) sAlpha[p] *= inv;
    }
    __syncthreads();
    bool act = t < declen[b];
    if (tid < Pz) o_alpha[((size_t)b * Tz + t) * Pz + tid] = act ? sAlpha[tid] : 0.f;
    const float* ifb = IF + (size_t)b * Pz * Fz;
    for (int f = tid; f < Fz; f += 256) {
        float sv = 0.f;
        for (int p = 0; p < Pz; p++) sv = fmaf(sAlpha[p], ifb[p * Fz + f], sv);
        split2(sv, aweh + b * Fz + f, awel + b * Fz + f);
    }
}

// ---------- launch ----------
extern "C" void kernel_launch(void* const* d_in, const int* in_sizes, int n_in,
                              void* d_out, int out_size)
{
    const float* img_att = (const float*)d_in[0];
    const float* img_fc  = (const float*)d_in[1];
    const int*   enc     = (const int*)d_in[2];
    const int*   caplen  = (const int*)d_in[3];
    const float* emb     = (const float*)d_in[4];
    const float* Wfa     = (const float*)d_in[5];
    const float* bfa     = (const float*)d_in[6];
    const float* Wd1     = (const float*)d_in[7];
    const float* bd1     = (const float*)d_in[8];
    const float* Wd2     = (const float*)d_in[9];
    const float* bd2     = (const float*)d_in[10];
    const float* Wfull   = (const float*)d_in[11];
    const float* Wlang   = (const float*)d_in[13];
    const float* blang   = (const float*)d_in[14];
    const float* Watt    = (const float*)d_in[15];
    const float* batt    = (const float*)d_in[16];
    const float* Wout    = (const float*)d_in[17];
    const float* bout    = (const float*)d_in[18];
    const float* Wll_ih  = (const float*)d_in[19];
    const float* Wll_hh  = (const float*)d_in[20];
    const float* bll     = (const float*)d_in[21];
    const float* Wal_ih  = (const float*)d_in[22];
    const float* Wal_hh  = (const float*)d_in[23];
    const float* bal     = (const float*)d_in[24];
    const float* Wfc     = (const float*)d_in[25];
    const float* bfc     = (const float*)d_in[26];

    void* pf; cudaGetSymbolAddress(&pf, g_fs);
    void* ph; cudaGetSymbolAddress(&ph, g_hb);
    void* pi; cudaGetSymbolAddress(&pi, g_is);
    float* fs = (float*)pf;
    bf*    hb = (bf*)ph;
    int*   is = (int*)pi;
    cudaFuncSetAttribute(gemm_ms, cudaFuncAttributeMaxDynamicSharedMemorySize, GSM);

    float* IF    = fs + FS_IF;
    float* imgfc = fs + FS_IMGFC;
    float* att1  = fs + FS_ATT1;
    float* Eall  = fs + FS_EALL;
    float* gfc   = fs + FS_GFC;
    float* proj  = fs + FS_PROJ;
    float* c1    = fs + FS_C1;
    float* c2    = fs + FS_C2;
    float* projb = fs + FS_PROJB;
    float* hidb  = fs + FS_HIDB;
    float* part  = fs + FS_PART;
    int* sortp = is, *declenp = is + 128, *capsp = is + 256;

    float* o_pred  = (float*)d_out;
    float* o_pred1 = o_pred + (size_t)Bz * Tz * Vz;
    float* o_caps  = o_pred1 + (size_t)Bz * Tz * Vz;
    float* o_dlen  = o_caps + Bz * Lz;
    float* o_alpha = o_dlen + Bz;
    float* o_sort  = o_alpha + (size_t)Bz * Tz * Pz;

    sort_kernel<<<1, 128>>>(caplen, enc, sortp, declenp, capsp, o_caps, o_dlen, o_sort);
    gather_kernel<<<Bz * Pz, 256>>>(img_att, img_fc, sortp, IF, imgfc);
    gather_emb<<<Tz * Bz, 256>>>(emb, capsp, hb + HB_EMBG, hb + HB_EMBG + 2490368);
    zero_init<<<1024, 256>>>(c1, c2, hb + HB_H1, hb + HB_H2);
    make_bias<<<4, 256>>>(bd1, bd2, blang, batt, projb, hidb);

#define CVT(src, ls, srcR, R, C, base) \
    convert_split<<<((size_t)(R)*(C) + 255) / 256, 256>>>(src, ls, srcR, (R)*(C), C, hb + (base), hb + (base) + (size_t)(R)*(C))
    CVT(Wfa, 2048, 1024, 1024, 2048, HB_WFA);
    CVT(Wll_ih + 0,    4096, 4096, 4096, 1024, HB_WE);
    CVT(Wll_ih + 1024, 4096, 4096, 4096, 1024, HB_WH);
    CVT(Wll_ih + 2048, 4096, 4096, 4096, 2048, HB_WF);
    CVT(Wll_hh, 1024, 4096, 4096, 1024, HB_WHH);
    CVT(Wal_ih, 2048, 4096, 4096, 2048, HB_WALI);
    CVT(Wal_hh, 1024, 4096, 4096, 1024, HB_WALH);
    CVT(Wd1, 1024, 1024, 1024, 1024, HB_WD1);
    CVT(Wd2, 1024, 1024, 1024, 1024, HB_WD2);
    CVT(Wlang, 1024, 512, 512, 1024, HB_WLANG);
    CVT(Watt,  1024, 512, 512, 1024, HB_WATT);
    CVT(Wfc,  1024, 10000, 10240, 1024, HB_WFCP);
    CVT(Wout, 1024, 10000, 10240, 1024, HB_WOUTP);
    CVT(IF, 2048, 4736, 4736, 2048, HB_IF);
    CVT(imgfc, 2048, 128, 128, 2048, HB_IMGFC);
#undef CVT

#define HBP(o, n) hb + (o), hb + (o) + (n)
    // att1 = IF@Wfa^T, M=4736 (raw), then +bfa in place
    gemm_ms<<<dim3(8, 37, 1), 256, GSM>>>(
        HBP(HB_IF, 9699328), HBP(HB_WFA, 2097152), 2048, 1, 8, 0, 0,
        hb, hb, hb, hb, 0, 0, 0, 0, 0, att1, 1024, 4849664);
    finish_linear<<<18944, 256>>>(att1, 1, 0, 1024, bfa, 0, nullptr, 0,
                                  att1, 1024, nullptr, nullptr, 4736, 1024);
    // Eall = embg@We^T, M=2432
    gemm_ms<<<dim3(32, 19, 1), 256, GSM>>>(
        HBP(HB_EMBG, 2490368), HBP(HB_WE, 4194304), 1024, 1, 32, 0, 0,
        hb, hb, hb, hb, 0, 0, 0, 0, 0, Eall, 4096, 9961472);
    // gfc = imgfc@Wf^T
    gemm_ms<<<dim3(32, 1, 2), 256, GSM>>>(
        HBP(HB_IMGFC, 262144), HBP(HB_WF, 8388608), 2048, 2, 32, 0, 0,
        hb, hb, hb, hb, 0, 0, 0, 0, 0, part, 4096, 524288);
    finish_linear<<<2048, 256>>>(part, 2, 524288, 4096, nullptr, 0, nullptr, 0,
                                 gfc, 4096, nullptr, nullptr, 128, 4096);

    for (int t = 0; t < Tz; t++) {
        // gates1: h2@Wh (sl 0,1) + h1@Whh (sl 2,3)
        gemm_ms<<<dim3(64, 1, 2), 256, GSM>>>(
            HBP(HB_H2, 131072), HBP(HB_WH, 4194304), 1024, 2, 32, 0, 0,
            HBP(HB_H1, 131072), HBP(HB_WHH, 4194304), 1024, 2, 32, 0, 2,
            part, 4096, 524288);
        finish_lstm<<<512, 256>>>(part, 4, 524288, gfc, Eall + (size_t)t * 524288, bll,
                                  c1, HBP(HB_H1, 131072), HBP(HB_H1N, 131072), declenp, t);
        // preds1 = h1n@Wfc^T
        gemm_ms<<<dim3(80, 1, 2), 256, GSM>>>(
            HBP(HB_H1N, 131072), HBP(HB_WFCP, 10485760), 1024, 2, 80, 0, 0,
            hb, hb, hb, hb, 0, 0, 0, 0, 0, part, 10240, 1310720);
        finish_linear<<<5000, 256>>>(part, 2, 1310720, 10240, bfc, 0, declenp, t,
                                     o_pred1 + (size_t)t * Vz, Tz * Vz, nullptr, nullptr, 128, Vz);
        // proj = h1n@Wd1^T + h2@Wd2^T
        gemm_ms<<<dim3(16, 1, 2), 256, GSM>>>(
            HBP(HB_H1N, 131072), HBP(HB_WD1, 1048576), 1024, 2, 8, 0, 0,
            HBP(HB_H2, 131072), HBP(HB_WD2, 1048576), 1024, 2, 8, 0, 2,
            part, 1024, 131072);
        finish_linear<<<512, 256>>>(part, 4, 131072, 1024, projb, 0, nullptr, 0,
                                    proj, 1024, nullptr, nullptr, 128, 1024);
        attention_kernel<<<Bz, 256>>>(att1, proj, Wfull, IF,
                                      hb + HB_AWE, hb + HB_AWE + 262144, o_alpha, declenp, t);
        // gates2: awe@Wal_ih (sl 0,1) + h2@Wal_hh (sl 2,3)
        gemm_ms<<<dim3(64, 1, 2), 256, GSM>>>(
            HBP(HB_AWE, 262144), HBP(HB_WALI, 8388608), 2048, 2, 32, 0, 0,
            HBP(HB_H2, 131072), HBP(HB_WALH, 4194304), 1024, 2, 32, 0, 2,
            part, 4096, 524288);
        finish_lstm<<<512, 256>>>(part, 4, 524288, nullptr, nullptr, bal,
                                  c2, HBP(HB_H2, 131072), HBP(HB_H2N, 131072), declenp, t);
        // hid: h1n@Wlang (cols 0..511) | h2n@Watt (cols 512..1023, W row-rebased)
        gemm_ms<<<dim3(8, 1, 2), 256, GSM>>>(
            HBP(HB_H1N, 131072), HBP(HB_WLANG, 524288), 1024, 2, 4, 0, 0,
            HBP(HB_H2N, 131072), hb + HB_WATT - 524288, hb + HB_WATT, 1024, 2, 4, 512, 0,
            part, 1024, 131072);
        finish_linear<<<512, 256>>>(part, 2, 131072, 1024, hidb, 1, nullptr, 0,
                                    nullptr, 0, hb + HB_HID, hb + HB_HID + 131072, 128, 1024);
        // out = hid@Wout^T
        gemm_ms<<<dim3(80, 1, 2), 256, GSM>>>(
            HBP(HB_HID, 131072), HBP(HB_WOUTP, 10485760), 1024, 2, 80, 0, 0,
            hb, hb, hb, hb, 0, 0, 0, 0, 0, part, 10240, 1310720);
        finish_linear<<<5000, 256>>>(part, 2, 1310720, 10240, bout, 0, declenp, t,
                                     o_pred + (size_t)t * Vz, Tz * Vz, nullptr, nullptr, 128, Vz);
    }
#undef HBP
}

// round 10
// speedup vs baseline: 5.9768x; 1.4798x over previous
#include <cuda_runtime.h>
#include <cuda_bf16.h>
#include <cstdint>

typedef __nv_bfloat16 bf;
#define Bz 128
#define Pz 37
#define Fz 2048
#define Vz 10000
#define Lz 20
#define Tz 19

#define TILEB 10240
#define BUFB  40960
#define GSM   81920

__device__ __forceinline__ uint32_t smem_u32(const void* p) {
    uint32_t a;
    asm("{ .reg .u64 t; cvta.to.shared.u64 t, %1; cvt.u32.u64 %0, t; }" : "=r"(a) : "l"(p));
    return a;
}

#define LDMX4(R, addr) \
    asm volatile("ldmatrix.sync.aligned.m8n8.x4.shared.b16 {%0,%1,%2,%3}, [%4];" \
        : "=r"((R)[0]), "=r"((R)[1]), "=r"((R)[2]), "=r"((R)[3]) : "r"(addr))

#define MMA(C, A, B) \
    asm volatile("mma.sync.aligned.m16n8k16.row.col.f32.bf16.bf16.f32 " \
        "{%0,%1,%2,%3},{%4,%5,%6,%7},{%8,%9},{%0,%1,%2,%3};" \
        : "+f"((C)[0]), "+f"((C)[1]), "+f"((C)[2]), "+f"((C)[3]) \
        : "r"((A)[0]), "r"((A)[1]), "r"((A)[2]), "r"((A)[3]), "r"((B)[0]), "r"((B)[1]))

#define CPA(d, g) \
    asm volatile("cp.async.cg.shared.global [%0], [%1], 16;" :: "r"(d), "l"(g))

// ---------- static device memory ----------
__device__ float g_fs[28313600];
__device__ bf    g_hb[146800640];
__device__ int   g_is[4096];

#define FS_IF     0
#define FS_IMGFC  9699328
#define FS_ATT1   9961472
#define FS_EALL   14811136
#define FS_GFC    24772608
#define FS_C1     25427968
#define FS_C2     25559040
#define FS_PROJB  25690112
#define FS_HIDB   25691136
#define FS_PART   25692160

#define HB_WFA    0
#define HB_WE     4194304
#define HB_WH     12582912
#define HB_WF     20971520
#define HB_WHH    37748736
#define HB_WALI   46137344
#define HB_WALH   62914560
#define HB_WD1    71303168
#define HB_WD2    73400320
#define HB_WLANG  75497472
#define HB_WATT   76546048
#define HB_WFCP   77594624
#define HB_WOUTP  98566144
#define HB_IF     119537664
#define HB_IMGFC  138936320
#define HB_EMBG   139460608
#define HB_H1     144441344
#define HB_H2     144703488
#define HB_H1N    144965632
#define HB_H2N    145227776
#define HB_AWE    145489920
#define HB_HID    146014208
#define HB_H1N2   146276352
#define HB_HID2   146538496

__device__ __forceinline__ void split2(float v, bf* dh, bf* dl) {
    bf h = __float2bfloat16(v);
    *dh = h;
    *dl = __float2bfloat16(v - __bfloat162float(h));
}

// ---------- preprocessing ----------
__global__ void sort_kernel(const int* __restrict__ caplen, const int* __restrict__ enc,
                            int* sortp, int* declenp, int* capsp,
                            float* o_caps, float* o_dlen, float* o_sort)
{
    __shared__ int len[Bz];
    int i = threadIdx.x;
    len[i] = caplen[i];
    __syncthreads();
    int li = len[i], rank = 0;
    for (int j = 0; j < Bz; j++) {
        int lj = len[j];
        rank += (lj > li) || (lj == li && j < i);
    }
    sortp[rank] = i;
    __syncthreads();
    int src = sortp[i];
    int dl = len[src] - 1;
    declenp[i] = dl;
    o_dlen[i] = (float)dl;
    o_sort[i] = (float)src;
    for (int k = 0; k < Lz; k++) {
        int c = enc[src * Lz + k];
        capsp[i * Lz + k] = c;
        o_caps[i * Lz + k] = (float)c;
    }
}

__global__ void gather_kernel(const float* __restrict__ img_att, const float* __restrict__ img_fc,
                              const int* __restrict__ sortp, float* IF, float* imgfc)
{
    int bp = blockIdx.x, b = bp / Pz, p = bp % Pz;
    int src = sortp[b];
    const float* s = (p < 36) ? (img_att + ((size_t)src * 36 + p) * Fz) : (img_fc + (size_t)src * Fz);
    float* d = IF + (size_t)bp * Fz;
    for (int f = threadIdx.x; f < Fz; f += blockDim.x) d[f] = s[f];
    if (p == 36) {
        float* d2 = imgfc + (size_t)b * Fz;
        for (int f = threadIdx.x; f < Fz; f += blockDim.x) d2[f] = s[f];
    }
}

__global__ void gather_emb(const float* __restrict__ emb, const int* __restrict__ caps,
                           bf* dh, bf* dl)
{
    int r = blockIdx.x, t = r >> 7, b = r & 127;
    const float* s = emb + (size_t)caps[b * Lz + t] * 1024;
    for (int c = threadIdx.x; c < 1024; c += blockDim.x)
        split2(s[c], dh + (size_t)r * 1024 + c, dl + (size_t)r * 1024 + c);
}

__global__ void convert_split(const float* __restrict__ src, int ls, int srcR, int n, int C,
                              bf* dh, bf* dl)
{
    int i = blockIdx.x * blockDim.x + threadIdx.x;
    if (i >= n) return;
    int r = i / C, c = i % C;
    float v = (r < srcR) ? src[(size_t)r * ls + c] : 0.f;
    split2(v, dh + i, dl + i);
}

__global__ void make_bias(const float* bd1, const float* bd2, const float* blang,
                          const float* batt, float* projb, float* hidb)
{
    int i = blockIdx.x * blockDim.x + threadIdx.x;
    if (i < 1024) {
        projb[i] = bd1[i] + bd2[i];
        hidb[i] = (i < 512) ? blang[i] : batt[i - 512];
    }
}

__global__ void zero_init(float* c1, float* c2, bf* h1, bf* h2)
{
    int i = blockIdx.x * blockDim.x + threadIdx.x;
    if (i < 262144) {
        h1[i] = __float2bfloat16(0.f);
        h2[i] = __float2bfloat16(0.f);
        if (i < 131072) { c1[i] = 0.f; c2[i] = 0.f; }
    }
}

// ---------- generic mma.sync GEMM ----------
// Two job slots (column ranges); each job up to 2 accumulated K-passes.
// S>1: write fp32 partial per slice.  S==1: fused bias/mask epilogue -> outF.
struct GA {
    const bf* p[2][2][4];   // [job][pass][Ah,Al,Wh,Wl]
    int K[2][2];
    int NT1, n01, n02, S;
    float* partial; int ldP, ss;
    const float* bias;
    const int* declen; int t;
    float* outF; long long ldo; int Nvalid;
};

__global__ void __launch_bounds__(256, 1) gemm_ms(GA g)
{
    extern __shared__ char smem[];
    const int bx = blockIdx.x;
    const int job = (bx < g.NT1) ? 0 : 1;
    const int n0 = job ? g.n02 + (bx - g.NT1) * 128 : g.n01 + bx * 128;
    const int m0 = blockIdx.y * 128;
    const int s = blockIdx.z;
    const int K1g = g.K[job][0], K2g = g.K[job][1];
    const int Ks1 = K1g / g.S, Ks2 = K2g ? K2g / g.S : 0;
    const int NC1 = Ks1 >> 5, NCt = NC1 + (Ks2 >> 5);

    const int tid = threadIdx.x, lane = tid & 31, warp = tid >> 5;
    const int wm = warp >> 2, wn = warp & 3;
    const uint32_t sbase = smem_u32(smem);

    const int tile = tid >> 6, u0 = tid & 63, r0 = u0 >> 2, c0 = u0 & 3;
    const int rb = (tile < 2) ? m0 : n0;
    const bf* b1 = g.p[job][0][tile] + (size_t)(rb + r0) * K1g + s * Ks1 + c0 * 8;
    const size_t st1 = (size_t)16 * K1g;
    const bf* b2 = K2g ? (g.p[job][1][tile] + (size_t)(rb + r0) * K2g + s * Ks2 + c0 * 8) : (const bf*)0;
    const size_t st2 = (size_t)16 * K2g;
    const uint32_t dbase = sbase + tile * TILEB + r0 * 80 + c0 * 16;

    const int arow = (lane & 7) + ((lane >> 3) & 1) * 8;
    const uint32_t akoff = (uint32_t)((lane >> 4) * 16);
    const int brow = (lane & 7) + ((lane >> 4) << 3);
    const uint32_t bkoff = (uint32_t)(((lane >> 3) & 1) * 16);
    const uint32_t aoff = (uint32_t)((wm * 64 + arow) * 80) + akoff;
    const uint32_t boff = 2u * TILEB + (uint32_t)((wn * 32 + brow) * 80) + bkoff;

    float acc[4][4][4] = {};

    {   // prologue: chunk 0 (always pass 1)
        uint32_t d = dbase;
#pragma unroll
        for (int j = 0; j < 8; j++) CPA(d + j * 1280, b1 + (size_t)j * st1);
        asm volatile("cp.async.commit_group;" ::: "memory");
    }
    for (int c = 0; c < NCt; c++) {
        if (c + 1 < NCt) {
            const bf* gp; size_t st;
            if (c + 1 < NC1) { gp = b1 + (size_t)(c + 1) * 32; st = st1; }
            else             { gp = b2 + (size_t)(c + 1 - NC1) * 32; st = st2; }
            uint32_t d = dbase + ((c + 1) & 1) * BUFB;
#pragma unroll
            for (int j = 0; j < 8; j++) CPA(d + j * 1280, gp + (size_t)j * st);
            asm volatile("cp.async.commit_group;" ::: "memory");
            asm volatile("cp.async.wait_group 1;" ::: "memory");
        } else {
            asm volatile("cp.async.wait_group 0;" ::: "memory");
        }
        __syncthreads();
        const uint32_t sc = sbase + (c & 1) * BUFB;
#pragma unroll
        for (int kk = 0; kk < 2; kk++) {
            const uint32_t kb = kk * 32;
            uint32_t Bh[8], Bl[8];
#pragma unroll
            for (int p = 0; p < 2; p++) {
                LDMX4(&Bh[4 * p], sc + boff + p * 1280 + kb);
                LDMX4(&Bl[4 * p], sc + boff + TILEB + p * 1280 + kb);
            }
#pragma unroll
            for (int mt = 0; mt < 4; mt++) {
                uint32_t Af[4], Ag[4];
                LDMX4(Af, sc + aoff + mt * 1280 + kb);
                LDMX4(Ag, sc + aoff + TILEB + mt * 1280 + kb);
#pragma unroll
                for (int nt = 0; nt < 4; nt++) {
                    MMA(acc[mt][nt], Af, &Bh[2 * nt]);
                    MMA(acc[mt][nt], Af, &Bl[2 * nt]);
                    MMA(acc[mt][nt], Ag, &Bh[2 * nt]);
                }
            }
        }
        __syncthreads();
    }
    const int rr = lane >> 2, cc = (lane & 3) * 2;
    if (g.S > 1) {
        float* op = g.partial + (size_t)s * g.ss;
#pragma unroll
        for (int mt = 0; mt < 4; mt++) {
            int row = m0 + wm * 64 + mt * 16 + rr;
#pragma unroll
            for (int nt = 0; nt < 4; nt++) {
                int col = n0 + wn * 32 + nt * 8 + cc;
                *(float2*)(op + (size_t)row * g.ldP + col) = make_float2(acc[mt][nt][0], acc[mt][nt][1]);
                *(float2*)(op + (size_t)(row + 8) * g.ldP + col) = make_float2(acc[mt][nt][2], acc[mt][nt][3]);
            }
        }
    } else {
#pragma unroll
        for (int mt = 0; mt < 4; mt++) {
            int row = m0 + wm * 64 + mt * 16 + rr;
            bool a0 = !g.declen || (g.t < g.declen[row]);
            bool a1 = !g.declen || (g.t < g.declen[row + 8]);
#pragma unroll
            for (int nt = 0; nt < 4; nt++) {
                int col = n0 + wn * 32 + nt * 8 + cc;
                if (col < g.Nvalid) {
                    float bb0 = g.bias ? g.bias[col] : 0.f;
                    float bb1 = g.bias ? g.bias[col + 1] : 0.f;
                    float v0 = acc[mt][nt][0] + bb0, v1 = acc[mt][nt][1] + bb1;
                    float v2 = acc[mt][nt][2] + bb0, v3 = acc[mt][nt][3] + bb1;
                    if (!a0) { v0 = 0.f; v1 = 0.f; }
                    if (!a1) { v2 = 0.f; v3 = 0.f; }
                    *(float2*)(g.outF + (size_t)row * g.ldo + col) = make_float2(v0, v1);
                    *(float2*)(g.outF + (size_t)(row + 8) * g.ldo + col) = make_float2(v2, v3);
                }
            }
        }
    }
}

// ---------- finish kernels ----------
__global__ void finish_linear(const float* __restrict__ P, int Z, int ss, int ldP,
                              const float* __restrict__ bias, int relu,
                              float* __restrict__ outF, int ldo,
                              bf* dh, bf* dl, int M, int N)
{
    int i = blockIdx.x * blockDim.x + threadIdx.x;
    if (i >= M * N) return;
    int m = i / N, n = i % N;
    float v = bias ? bias[n] : 0.f;
    const float* p = P + (size_t)m * ldP + n;
    for (int z = 0; z < Z; z++) v += p[(size_t)z * ss];
    if (relu) v = fmaxf(v, 0.f);
    if (outF) outF[(size_t)m * ldo + n] = v;
    if (dh) split2(v, dh + i, dl + i);
}

__global__ void finish_lstm(const float* __restrict__ P, int Z, int ss,
                            const float* __restrict__ addA, const float* __restrict__ addB,
                            const float* __restrict__ bias, float* __restrict__ cst,
                            bf* hh, bf* hl, bf* hnh, bf* hnl,
                            const int* __restrict__ declen, int t)
{
    int idx = blockIdx.x * blockDim.x + threadIdx.x;
    if (idx >= Bz * 1024) return;
    int b = idx >> 10, d = idx & 1023;
    float g4[4];
#pragma unroll
    for (int q = 0; q < 4; q++) {
        int n = d + q * 1024;
        float v = bias[n];
        if (addA) v += addA[b * 4096 + n];
        if (addB) v += addB[b * 4096 + n];
        for (int z = 0; z < Z; z++) v += P[(size_t)z * ss + b * 4096 + n];
        g4[q] = v;
    }
    float si = 1.f / (1.f + expf(-g4[0]));
    float sf = 1.f / (1.f + expf(-g4[1]));
    float so = 1.f / (1.f + expf(-g4[3]));
    float cn = sf * cst[idx] + si * tanhf(g4[2]);
    float hv = so * tanhf(cn);
    split2(hv, hnh + idx, hnl + idx);
    if (t < declen[b]) { cst[idx] = cn; split2(hv, hh + idx, hl + idx); }
}

// ---------- attention (sums proj split-K slices itself) ----------
__global__ void __launch_bounds__(256)
attention_kernel(const float* __restrict__ att1, const float* __restrict__ projP,
                 int Zp, int ssP, const float* __restrict__ projb,
                 const float* __restrict__ Wfull, const float* __restrict__ IF,
                 bf* aweh, bf* awel, float* __restrict__ o_alpha,
                 const int* __restrict__ declen, int t)
{
    int b = blockIdx.x, tid = threadIdx.x;
    __shared__ float sW[1024], sP[1024], sScore[Pz], sAlpha[Pz], red[8];
    for (int a = tid; a < 1024; a += 256) {
        sW[a] = Wfull[a];
        float v = projb[a];
        const float* pp = projP + b * 1024 + a;
        for (int z = 0; z < Zp; z++) v += pp[(size_t)z * ssP];
        sP[a] = v;
    }
    __syncthreads();
    const float* att = att1 + (size_t)b * Pz * 1024;
    for (int p = 0; p < Pz; p++) {
        float part = 0.f;
        for (int a = tid; a < 1024; a += 256) {
            float e = fmaxf(att[p * 1024 + a] + sP[a], 0.f);
            part = fmaf(e, sW[a], part);
        }
        for (int o = 16; o; o >>= 1) part += __shfl_down_sync(0xffffffffu, part, o);
        if ((tid & 31) == 0) red[tid >> 5] = part;
        __syncthreads();
        if (tid == 0) {
            float ssum = 0.f;
            for (int w = 0; w < 8; w++) ssum += red[w];
            sScore[p] = ssum;
        }
        __syncthreads();
    }
    if (tid == 0) {
        float mx = sScore[0];
        for (int p = 1; p < Pz; p++) mx = fmaxf(mx, sScore[p]);
        float sum = 0.f;
        for (int p = 0; p < Pz; p++) { float e = expf(sScore[p] - mx); sAlpha[p] = e; sum += e; }
        float inv = 1.f / sum;
        for (int p = 0; p < Pz; p++) sAlpha[p] *= inv;
    }
    __syncthreads();
    bool act = t < declen[b];
    if (tid < Pz) o_alpha[((size_t)b * Tz + t) * Pz + tid] = act ? sAlpha[tid] : 0.f;
    const float* ifb = IF + (size_t)b * Pz * Fz;
    for (int f = tid; f < Fz; f += 256) {
        float sv = 0.f;
        for (int p = 0; p < Pz; p++) sv = fmaf(sAlpha[p], ifb[p * Fz + f], sv);
        split2(sv, aweh + b * Fz + f, awel + b * Fz + f);
    }
}

// ---------- launch ----------
extern "C" void kernel_launch(void* const* d_in, const int* in_sizes, int n_in,
                              void* d_out, int out_size)
{
    const float* img_att = (const float*)d_in[0];
    const float* img_fc  = (const float*)d_in[1];
    const int*   enc     = (const int*)d_in[2];
    const int*   caplen  = (const int*)d_in[3];
    const float* emb     = (const float*)d_in[4];
    const float* Wfa     = (const float*)d_in[5];
    const float* bfa     = (const float*)d_in[6];
    const float* Wd1     = (const float*)d_in[7];
    const float* bd1     = (const float*)d_in[8];
    const float* Wd2     = (const float*)d_in[9];
    const float* bd2     = (const float*)d_in[10];
    const float* Wfull   = (const float*)d_in[11];
    const float* Wlang   = (const float*)d_in[13];
    const float* blang   = (const float*)d_in[14];
    const float* Watt    = (const float*)d_in[15];
    const float* batt    = (const float*)d_in[16];
    const float* Wout    = (const float*)d_in[17];
    const float* bout    = (const float*)d_in[18];
    const float* Wll_ih  = (const float*)d_in[19];
    const float* Wll_hh  = (const float*)d_in[20];
    const float* bll     = (const float*)d_in[21];
    const float* Wal_ih  = (const float*)d_in[22];
    const float* Wal_hh  = (const float*)d_in[23];
    const float* bal     = (const float*)d_in[24];
    const float* Wfc     = (const float*)d_in[25];
    const float* bfc     = (const float*)d_in[26];

    void* pf; cudaGetSymbolAddress(&pf, g_fs);
    void* ph; cudaGetSymbolAddress(&ph, g_hb);
    void* pi; cudaGetSymbolAddress(&pi, g_is);
    float* fs = (float*)pf;
    bf*    hb = (bf*)ph;
    int*   is = (int*)pi;
    cudaFuncSetAttribute(gemm_ms, cudaFuncAttributeMaxDynamicSharedMemorySize, GSM);

    // streams/events: created once on first (non-captured correctness) call
    static cudaStream_t s1 = nullptr, s2 = nullptr;
    static cudaEvent_t evS, evF, evA, evE, evL[2], evP[2], evHd[2], evO[2];
    if (!s1) {
        cudaStreamCreateWithFlags(&s1, cudaStreamNonBlocking);
        cudaStreamCreateWithFlags(&s2, cudaStreamNonBlocking);
        cudaEventCreateWithFlags(&evS, cudaEventDisableTiming);
        cudaEventCreateWithFlags(&evF, cudaEventDisableTiming);
        cudaEventCreateWithFlags(&evA, cudaEventDisableTiming);
        cudaEventCreateWithFlags(&evE, cudaEventDisableTiming);
        for (int i = 0; i < 2; i++) {
            cudaEventCreateWithFlags(&evL[i], cudaEventDisableTiming);
            cudaEventCreateWithFlags(&evP[i], cudaEventDisableTiming);
            cudaEventCreateWithFlags(&evHd[i], cudaEventDisableTiming);
            cudaEventCreateWithFlags(&evO[i], cudaEventDisableTiming);
        }
    }

    float* IF    = fs + FS_IF;
    float* imgfc = fs + FS_IMGFC;
    float* att1  = fs + FS_ATT1;
    float* Eall  = fs + FS_EALL;
    float* gfc   = fs + FS_GFC;
    float* c1    = fs + FS_C1;
    float* c2    = fs + FS_C2;
    float* projb = fs + FS_PROJB;
    float* hidb  = fs + FS_HIDB;
    float* part  = fs + FS_PART;
    int* sortp = is, *declenp = is + 128, *capsp = is + 256;

    float* o_pred  = (float*)d_out;
    float* o_pred1 = o_pred + (size_t)Bz * Tz * Vz;
    float* o_caps  = o_pred1 + (size_t)Bz * Tz * Vz;
    float* o_dlen  = o_caps + Bz * Lz;
    float* o_alpha = o_dlen + Bz;
    float* o_sort  = o_alpha + (size_t)Bz * Tz * Pz;

    // fork side streams for the two 10M-element weight conversions
    cudaEventRecord(evS, 0);
    cudaStreamWaitEvent(s1, evS, 0);
    cudaStreamWaitEvent(s2, evS, 0);

#define CVTS(st, src, ls, srcR, R, C, base) \
    convert_split<<<((size_t)(R)*(C) + 255) / 256, 256, 0, st>>>(src, ls, srcR, (R)*(C), C, hb + (base), hb + (base) + (size_t)(R)*(C))
    CVTS(s1, Wfc,  1024, 10000, 10240, 1024, HB_WFCP);
    CVTS(s2, Wout, 1024, 10000, 10240, 1024, HB_WOUTP);

    sort_kernel<<<1, 128>>>(caplen, enc, sortp, declenp, capsp, o_caps, o_dlen, o_sort);
    gather_kernel<<<Bz * Pz, 256>>>(img_att, img_fc, sortp, IF, imgfc);
    gather_emb<<<Tz * Bz, 256>>>(emb, capsp, hb + HB_EMBG, hb + HB_EMBG + 2490368);
    zero_init<<<1024, 256>>>(c1, c2, hb + HB_H1, hb + HB_H2);
    make_bias<<<4, 256>>>(bd1, bd2, blang, batt, projb, hidb);
    CVTS((cudaStream_t)0, Wfa, 2048, 1024, 1024, 2048, HB_WFA);
    CVTS((cudaStream_t)0, Wll_ih + 0,    4096, 4096, 4096, 1024, HB_WE);
    CVTS((cudaStream_t)0, Wll_ih + 1024, 4096, 4096, 4096, 1024, HB_WH);
    CVTS((cudaStream_t)0, Wll_ih + 2048, 4096, 4096, 4096, 2048, HB_WF);
    CVTS((cudaStream_t)0, Wll_hh, 1024, 4096, 4096, 1024, HB_WHH);
    CVTS((cudaStream_t)0, Wal_ih, 2048, 4096, 4096, 2048, HB_WALI);
    CVTS((cudaStream_t)0, Wal_hh, 1024, 4096, 4096, 1024, HB_WALH);
    CVTS((cudaStream_t)0, Wd1, 1024, 1024, 1024, 1024, HB_WD1);
    CVTS((cudaStream_t)0, Wd2, 1024, 1024, 1024, 1024, HB_WD2);
    CVTS((cudaStream_t)0, Wlang, 1024, 512, 512, 1024, HB_WLANG);
    CVTS((cudaStream_t)0, Watt,  1024, 512, 512, 1024, HB_WATT);
    CVTS((cudaStream_t)0, IF, 2048, 4736, 4736, 2048, HB_IF);
    CVTS((cudaStream_t)0, imgfc, 2048, 128, 128, 2048, HB_IMGFC);
#undef CVTS
    cudaEventRecord(evF, 0);
    cudaStreamWaitEvent(s1, evF, 0);
    cudaStreamWaitEvent(s2, evF, 0);

    auto setJ = [](GA& g, int job, int pass, const bf* ah, const bf* al,
                   const bf* wh, const bf* wl, int K) {
        g.p[job][pass][0] = ah; g.p[job][pass][1] = al;
        g.p[job][pass][2] = wh; g.p[job][pass][3] = wl;
        g.K[job][pass] = K;
    };
#define HP(o, n) hb + (o), hb + (o) + (n)

    // Eall = embg@We^T (s1)
    {
        GA g = {};
        setJ(g, 0, 0, HP(HB_EMBG, 2490368), HP(HB_WE, 4194304), 1024);
        g.NT1 = 32; g.S = 1; g.outF = Eall; g.ldo = 4096; g.Nvalid = 4096;
        gemm_ms<<<dim3(32, 19, 1), 256, GSM, s1>>>(g);
        cudaEventRecord(evE, s1);
    }
    // att1 = IF@Wfa^T + bfa (s2)
    {
        GA g = {};
        setJ(g, 0, 0, HP(HB_IF, 9699328), HP(HB_WFA, 2097152), 2048);
        g.NT1 = 8; g.S = 1; g.bias = bfa; g.outF = att1; g.ldo = 1024; g.Nvalid = 1024;
        gemm_ms<<<dim3(8, 37, 1), 256, GSM, s2>>>(g);
        cudaEventRecord(evA, s2);
    }
    // gfc = imgfc@Wf^T (stream 0, overlaps the above)
    {
        GA g = {};
        setJ(g, 0, 0, HP(HB_IMGFC, 262144), HP(HB_WF, 8388608), 2048);
        g.NT1 = 32; g.S = 1; g.outF = gfc; g.ldo = 4096; g.Nvalid = 4096;
        gemm_ms<<<dim3(32, 1, 1), 256, GSM>>>(g);
    }
    cudaStreamWaitEvent(0, evE, 0);
    cudaStreamWaitEvent(0, evA, 0);

    const size_t H1N_O[2] = {HB_H1N, HB_H1N2};
    const size_t HID_O[2] = {HB_HID, HB_HID2};

    for (int t = 0; t < Tz; t++) {
        int pb = t & 1;
        if (t >= 2) cudaStreamWaitEvent(0, evP[pb], 0);
        // gates1 = h2@WH + h1@WHH, S=4
        {
            GA g = {};
            setJ(g, 0, 0, HP(HB_H2, 131072), HP(HB_WH, 4194304), 1024);
            setJ(g, 0, 1, HP(HB_H1, 131072), HP(HB_WHH, 4194304), 1024);
            g.NT1 = 32; g.S = 4; g.partial = part; g.ldP = 4096; g.ss = 524288;
            gemm_ms<<<dim3(32, 1, 4), 256, GSM>>>(g);
        }
        finish_lstm<<<512, 256>>>(part, 4, 524288, gfc, Eall + (size_t)t * 524288, bll,
                                  c1, HP(HB_H1, 131072), HP(H1N_O[pb], 131072), declenp, t);
        cudaEventRecord(evL[pb], 0);
        cudaStreamWaitEvent(s1, evL[pb], 0);
        // preds1 = h1n@Wfc^T + bfc (masked) -> o_pred1   [side stream]
        {
            GA g = {};
            setJ(g, 0, 0, HP(H1N_O[pb], 131072), HP(HB_WFCP, 10485760), 1024);
            g.NT1 = 80; g.S = 1; g.bias = bfc; g.declen = declenp; g.t = t;
            g.outF = o_pred1 + (size_t)t * Vz; g.ldo = (long long)Tz * Vz; g.Nvalid = Vz;
            gemm_ms<<<dim3(80, 1, 1), 256, GSM, s1>>>(g);
            cudaEventRecord(evP[pb], s1);
        }
        // proj = h1n@Wd1 + h2@Wd2, S=8 -> partial (summed inside attention)
        {
            GA g = {};
            setJ(g, 0, 0, HP(H1N_O[pb], 131072), HP(HB_WD1, 1048576), 1024);
            setJ(g, 0, 1, HP(HB_H2, 131072), HP(HB_WD2, 1048576), 1024);
            g.NT1 = 8; g.S = 8; g.partial = part; g.ldP = 1024; g.ss = 131072;
            gemm_ms<<<dim3(8, 1, 8), 256, GSM>>>(g);
        }
        attention_kernel<<<Bz, 256>>>(att1, part, 8, 131072, projb, Wfull, IF,
                                      hb + HB_AWE, hb + HB_AWE + 262144, o_alpha, declenp, t);
        // gates2 = awe@WALI + h2@WALH, S=4
        {
            GA g = {};
            setJ(g, 0, 0, HP(HB_AWE, 262144), HP(HB_WALI, 8388608), 2048);
            setJ(g, 0, 1, HP(HB_H2, 131072), HP(HB_WALH, 4194304), 1024);
            g.NT1 = 32; g.S = 4; g.partial = part; g.ldP = 4096; g.ss = 524288;
            gemm_ms<<<dim3(32, 1, 4), 256, GSM>>>(g);
        }
        finish_lstm<<<512, 256>>>(part, 4, 524288, nullptr, nullptr, bal,
                                  c2, HP(HB_H2, 131072), HP(HB_H2N, 131072), declenp, t);
        if (t >= 2) cudaStreamWaitEvent(0, evO[pb], 0);
        // hid: job1 h1n@Wlang (cols 0-511), job2 h2n@Watt (cols 512-1023), S=8
        {
            GA g = {};
            setJ(g, 0, 0, HP(H1N_O[pb], 131072), HP(HB_WLANG, 524288), 1024);
            setJ(g, 1, 0, HP(HB_H2N, 131072),
                 hb + HB_WATT - 524288, hb + HB_WATT, 1024);
            g.NT1 = 4; g.n01 = 0; g.n02 = 512; g.S = 8;
            g.partial = part; g.ldP = 1024; g.ss = 131072;
            gemm_ms<<<dim3(8, 1, 8), 256, GSM>>>(g);
        }
        finish_linear<<<512, 256>>>(part, 8, 131072, 1024, hidb, 1, nullptr, 0,
                                    hb + HID_O[pb], hb + HID_O[pb] + 131072, 128, 1024);
        cudaEventRecord(evHd[pb], 0);
        cudaStreamWaitEvent(s1, evHd[pb], 0);
        // out = hid@Wout^T + bout (masked) -> o_pred   [side stream]
        {
            GA g = {};
            setJ(g, 0, 0, HP(HID_O[pb], 131072), HP(HB_WOUTP, 10485760), 1024);
            g.NT1 = 80; g.S = 1; g.bias = bout; g.declen = declenp; g.t = t;
            g.outF = o_pred + (size_t)t * Vz; g.ldo = (long long)Tz * Vz; g.Nvalid = Vz;
            gemm_ms<<<dim3(80, 1, 1), 256, GSM, s1>>>(g);
            cudaEventRecord(evO[pb], s1);
        }
    }
    // join side stream before capture ends
    cudaStreamWaitEvent(0, evO[0], 0);
    cudaStreamWaitEvent(0, evO[1], 0);
#undef HP
}

// round 11
// speedup vs baseline: 7.9505x; 1.3302x over previous
#include <cuda_runtime.h>
#include <cuda_bf16.h>
#include <cstdint>

typedef __nv_bfloat16 bf;
#define Bz 128
#define Pz 37
#define Fz 2048
#define Vz 10000
#define Lz 20
#define Tz 19

#define TILEB 10240
#define BUFB  40960
#define GSM   81920

__device__ __forceinline__ uint32_t smem_u32(const void* p) {
    uint32_t a;
    asm("{ .reg .u64 t; cvta.to.shared.u64 t, %1; cvt.u32.u64 %0, t; }" : "=r"(a) : "l"(p));
    return a;
}

#define LDMX4(R, addr) \
    asm volatile("ldmatrix.sync.aligned.m8n8.x4.shared.b16 {%0,%1,%2,%3}, [%4];" \
        : "=r"((R)[0]), "=r"((R)[1]), "=r"((R)[2]), "=r"((R)[3]) : "r"(addr))

#define MMA(C, A, B) \
    asm volatile("mma.sync.aligned.m16n8k16.row.col.f32.bf16.bf16.f32 " \
        "{%0,%1,%2,%3},{%4,%5,%6,%7},{%8,%9},{%0,%1,%2,%3};" \
        : "+f"((C)[0]), "+f"((C)[1]), "+f"((C)[2]), "+f"((C)[3]) \
        : "r"((A)[0]), "r"((A)[1]), "r"((A)[2]), "r"((A)[3]), "r"((B)[0]), "r"((B)[1]))

#define CPA(d, g) \
    asm volatile("cp.async.cg.shared.global [%0], [%1], 16;" :: "r"(d), "l"(g))

// ---------- static device memory ----------
__device__ float g_fs[28966912];
__device__ bf    g_hb[147062784];
__device__ int   g_is[4096];

#define FS_IF     0
#define FS_IMGFC  9699328
#define FS_ATT1   9961472
#define FS_EALL   14811136
#define FS_GFC    24772608
#define FS_C1     25427968
#define FS_C2     25559040
#define FS_PROJB  25690112
#define FS_HIDB   25691136
#define FS_PART   25692160
#define FS_PARTB  27789312

#define HB_WFA    0
#define HB_WE     4194304
#define HB_WH     12582912
#define HB_WF     20971520
#define HB_WHH    37748736
#define HB_WALI   46137344
#define HB_WALH   62914560
#define HB_WD1    71303168
#define HB_WD2    73400320
#define HB_WLANG  75497472
#define HB_WATT   76546048
#define HB_WFCP   77594624
#define HB_WOUTP  98566144
#define HB_IF     119537664
#define HB_IMGFC  138936320
#define HB_EMBG   139460608
#define HB_H1     144441344
#define HB_H2     144703488
#define HB_H1N    144965632
#define HB_H2N    145227776
#define HB_AWE    145489920
#define HB_HID    146014208
#define HB_H1N2   146276352
#define HB_HID2   146538496
#define HB_H2N2   146800640

__device__ __forceinline__ void split2(float v, bf* dh, bf* dl) {
    bf h = __float2bfloat16(v);
    *dh = h;
    *dl = __float2bfloat16(v - __bfloat162float(h));
}

// ---------- preprocessing ----------
__global__ void sort_kernel(const int* __restrict__ caplen, const int* __restrict__ enc,
                            int* sortp, int* declenp, int* capsp,
                            float* o_caps, float* o_dlen, float* o_sort)
{
    __shared__ int len[Bz];
    int i = threadIdx.x;
    len[i] = caplen[i];
    __syncthreads();
    int li = len[i], rank = 0;
    for (int j = 0; j < Bz; j++) {
        int lj = len[j];
        rank += (lj > li) || (lj == li && j < i);
    }
    sortp[rank] = i;
    __syncthreads();
    int src = sortp[i];
    int dl = len[src] - 1;
    declenp[i] = dl;
    o_dlen[i] = (float)dl;
    o_sort[i] = (float)src;
    for (int k = 0; k < Lz; k++) {
        int c = enc[src * Lz + k];
        capsp[i * Lz + k] = c;
        o_caps[i * Lz + k] = (float)c;
    }
}

__global__ void gather_kernel(const float* __restrict__ img_att, const float* __restrict__ img_fc,
                              const int* __restrict__ sortp, float* IF, float* imgfc)
{
    int bp = blockIdx.x, b = bp / Pz, p = bp % Pz;
    int src = sortp[b];
    const float* s = (p < 36) ? (img_att + ((size_t)src * 36 + p) * Fz) : (img_fc + (size_t)src * Fz);
    float* d = IF + (size_t)bp * Fz;
    for (int f = threadIdx.x; f < Fz; f += blockDim.x) d[f] = s[f];
    if (p == 36) {
        float* d2 = imgfc + (size_t)b * Fz;
        for (int f = threadIdx.x; f < Fz; f += blockDim.x) d2[f] = s[f];
    }
}

__global__ void gather_emb(const float* __restrict__ emb, const int* __restrict__ caps,
                           bf* dh, bf* dl)
{
    int r = blockIdx.x, t = r >> 7, b = r & 127;
    const float* s = emb + (size_t)caps[b * Lz + t] * 1024;
    for (int c = threadIdx.x; c < 1024; c += blockDim.x)
        split2(s[c], dh + (size_t)r * 1024 + c, dl + (size_t)r * 1024 + c);
}

__global__ void convert_split(const float* __restrict__ src, int ls, int srcR, int n, int C,
                              bf* dh, bf* dl)
{
    int i = blockIdx.x * blockDim.x + threadIdx.x;
    if (i >= n) return;
    int r = i / C, c = i % C;
    float v = (r < srcR) ? src[(size_t)r * ls + c] : 0.f;
    split2(v, dh + i, dl + i);
}

__global__ void make_bias(const float* bd1, const float* bd2, const float* blang,
                          const float* batt, float* projb, float* hidb)
{
    int i = blockIdx.x * blockDim.x + threadIdx.x;
    if (i < 1024) {
        projb[i] = bd1[i] + bd2[i];
        hidb[i] = (i < 512) ? blang[i] : batt[i - 512];
    }
}

__global__ void zero_init(float* c1, float* c2, bf* h1, bf* h2)
{
    int i = blockIdx.x * blockDim.x + threadIdx.x;
    if (i < 262144) {
        h1[i] = __float2bfloat16(0.f);
        h2[i] = __float2bfloat16(0.f);
        if (i < 131072) { c1[i] = 0.f; c2[i] = 0.f; }
    }
}

// ---------- generic mma.sync GEMM ----------
struct GA {
    const bf* p[2][2][4];   // [job][pass][Ah,Al,Wh,Wl]
    int K[2][2];
    int NT1, n01, n02, S;
    float* partial; int ldP, ss;
    const float* bias;
    const int* declen; int t;
    float* outF; long long ldo; int Nvalid;
};

__global__ void __launch_bounds__(256, 1) gemm_ms(GA g)
{
    extern __shared__ char smem[];
    const int bx = blockIdx.x;
    const int job = (bx < g.NT1) ? 0 : 1;
    const int n0 = job ? g.n02 + (bx - g.NT1) * 128 : g.n01 + bx * 128;
    const int m0 = blockIdx.y * 128;
    const int s = blockIdx.z;
    const int K1g = g.K[job][0], K2g = g.K[job][1];
    const int Ks1 = K1g / g.S, Ks2 = K2g ? K2g / g.S : 0;
    const int NC1 = Ks1 >> 5, NCt = NC1 + (Ks2 >> 5);

    const int tid = threadIdx.x, lane = tid & 31, warp = tid >> 5;
    const int wm = warp >> 2, wn = warp & 3;
    const uint32_t sbase = smem_u32(smem);

    const int tile = tid >> 6, u0 = tid & 63, r0 = u0 >> 2, c0 = u0 & 3;
    const int rb = (tile < 2) ? m0 : n0;
    const bf* b1 = g.p[job][0][tile] + (size_t)(rb + r0) * K1g + s * Ks1 + c0 * 8;
    const size_t st1 = (size_t)16 * K1g;
    const bf* b2 = K2g ? (g.p[job][1][tile] + (size_t)(rb + r0) * K2g + s * Ks2 + c0 * 8) : (const bf*)0;
    const size_t st2 = (size_t)16 * K2g;
    const uint32_t dbase = sbase + tile * TILEB + r0 * 80 + c0 * 16;

    const int arow = (lane & 7) + ((lane >> 3) & 1) * 8;
    const uint32_t akoff = (uint32_t)((lane >> 4) * 16);
    const int brow = (lane & 7) + ((lane >> 4) << 3);
    const uint32_t bkoff = (uint32_t)(((lane >> 3) & 1) * 16);
    const uint32_t aoff = (uint32_t)((wm * 64 + arow) * 80) + akoff;
    const uint32_t boff = 2u * TILEB + (uint32_t)((wn * 32 + brow) * 80) + bkoff;

    float acc[4][4][4] = {};

    {
        uint32_t d = dbase;
#pragma unroll
        for (int j = 0; j < 8; j++) CPA(d + j * 1280, b1 + (size_t)j * st1);
        asm volatile("cp.async.commit_group;" ::: "memory");
    }
    for (int c = 0; c < NCt; c++) {
        if (c + 1 < NCt) {
            const bf* gp; size_t st;
            if (c + 1 < NC1) { gp = b1 + (size_t)(c + 1) * 32; st = st1; }
            else             { gp = b2 + (size_t)(c + 1 - NC1) * 32; st = st2; }
            uint32_t d = dbase + ((c + 1) & 1) * BUFB;
#pragma unroll
            for (int j = 0; j < 8; j++) CPA(d + j * 1280, gp + (size_t)j * st);
            asm volatile("cp.async.commit_group;" ::: "memory");
            asm volatile("cp.async.wait_group 1;" ::: "memory");
        } else {
            asm volatile("cp.async.wait_group 0;" ::: "memory");
        }
        __syncthreads();
        const uint32_t sc = sbase + (c & 1) * BUFB;
#pragma unroll
        for (int kk = 0; kk < 2; kk++) {
            const uint32_t kb = kk * 32;
            uint32_t Bh[8], Bl[8];
#pragma unroll
            for (int p = 0; p < 2; p++) {
                LDMX4(&Bh[4 * p], sc + boff + p * 1280 + kb);
                LDMX4(&Bl[4 * p], sc + boff + TILEB + p * 1280 + kb);
            }
#pragma unroll
            for (int mt = 0; mt < 4; mt++) {
                uint32_t Af[4], Ag[4];
                LDMX4(Af, sc + aoff + mt * 1280 + kb);
                LDMX4(Ag, sc + aoff + TILEB + mt * 1280 + kb);
#pragma unroll
                for (int nt = 0; nt < 4; nt++) {
                    MMA(acc[mt][nt], Af, &Bh[2 * nt]);
                    MMA(acc[mt][nt], Af, &Bl[2 * nt]);
                    MMA(acc[mt][nt], Ag, &Bh[2 * nt]);
                }
            }
        }
        __syncthreads();
    }
    const int rr = lane >> 2, cc = (lane & 3) * 2;
    if (g.S > 1) {
        float* op = g.partial + (size_t)s * g.ss;
#pragma unroll
        for (int mt = 0; mt < 4; mt++) {
            int row = m0 + wm * 64 + mt * 16 + rr;
#pragma unroll
            for (int nt = 0; nt < 4; nt++) {
                int col = n0 + wn * 32 + nt * 8 + cc;
                *(float2*)(op + (size_t)row * g.ldP + col) = make_float2(acc[mt][nt][0], acc[mt][nt][1]);
                *(float2*)(op + (size_t)(row + 8) * g.ldP + col) = make_float2(acc[mt][nt][2], acc[mt][nt][3]);
            }
        }
    } else {
#pragma unroll
        for (int mt = 0; mt < 4; mt++) {
            int row = m0 + wm * 64 + mt * 16 + rr;
            bool a0 = !g.declen || (g.t < g.declen[row]);
            bool a1 = !g.declen || (g.t < g.declen[row + 8]);
#pragma unroll
            for (int nt = 0; nt < 4; nt++) {
                int col = n0 + wn * 32 + nt * 8 + cc;
                if (col < g.Nvalid) {
                    float bb0 = g.bias ? g.bias[col] : 0.f;
                    float bb1 = g.bias ? g.bias[col + 1] : 0.f;
                    float v0 = acc[mt][nt][0] + bb0, v1 = acc[mt][nt][1] + bb1;
                    float v2 = acc[mt][nt][2] + bb0, v3 = acc[mt][nt][3] + bb1;
                    if (!a0) { v0 = 0.f; v1 = 0.f; }
                    if (!a1) { v2 = 0.f; v3 = 0.f; }
                    *(float2*)(g.outF + (size_t)row * g.ldo + col) = make_float2(v0, v1);
                    *(float2*)(g.outF + (size_t)(row + 8) * g.ldo + col) = make_float2(v2, v3);
                }
            }
        }
    }
}

// ---------- finish kernels ----------
__global__ void finish_linear(const float* __restrict__ P, int Z, int ss, int ldP,
                              const float* __restrict__ bias, int relu,
                              float* __restrict__ outF, int ldo,
                              bf* dh, bf* dl, int M, int N)
{
    int i = blockIdx.x * blockDim.x + threadIdx.x;
    if (i >= M * N) return;
    int m = i / N, n = i % N;
    float v = bias ? bias[n] : 0.f;
    const float* p = P + (size_t)m * ldP + n;
    for (int z = 0; z < Z; z++) v += p[(size_t)z * ss];
    if (relu) v = fmaxf(v, 0.f);
    if (outF) outF[(size_t)m * ldo + n] = v;
    if (dh) split2(v, dh + i, dl + i);
}

__global__ void finish_lstm(const float* __restrict__ P, int Z, int ss,
                            const float* __restrict__ addA, const float* __restrict__ addB,
                            const float* __restrict__ bias, float* __restrict__ cst,
                            bf* hh, bf* hl, bf* hnh, bf* hnl,
                            const int* __restrict__ declen, int t)
{
    int idx = blockIdx.x * blockDim.x + threadIdx.x;
    if (idx >= Bz * 1024) return;
    int b = idx >> 10, d = idx & 1023;
    float g4[4];
#pragma unroll
    for (int q = 0; q < 4; q++) {
        int n = d + q * 1024;
        float v = bias[n];
        if (addA) v += addA[b * 4096 + n];
        if (addB) v += addB[b * 4096 + n];
        for (int z = 0; z < Z; z++) v += P[(size_t)z * ss + b * 4096 + n];
        g4[q] = v;
    }
    float si = 1.f / (1.f + expf(-g4[0]));
    float sf = 1.f / (1.f + expf(-g4[1]));
    float so = 1.f / (1.f + expf(-g4[3]));
    float cn = sf * cst[idx] + si * tanhf(g4[2]);
    float hv = so * tanhf(cn);
    split2(hv, hnh + idx, hnl + idx);
    if (t < declen[b]) { cst[idx] = cn; split2(hv, hh + idx, hl + idx); }
}

// ---------- attention (512 threads, warp-parallel scores) ----------
__global__ void __launch_bounds__(512)
attention_kernel(const float* __restrict__ att1, const float* __restrict__ projP,
                 int Zp, int ssP, const float* __restrict__ projb,
                 const float* __restrict__ Wfull, const float* __restrict__ IF,
                 bf* aweh, bf* awel, float* __restrict__ o_alpha,
                 const int* __restrict__ declen, int t)
{
    int b = blockIdx.x, tid = threadIdx.x, lane = tid & 31, warp = tid >> 5;
    __shared__ float sW[1024], sP[1024], sScore[Pz], sAlpha[Pz];
    for (int a = tid; a < 1024; a += 512) {
        sW[a] = Wfull[a];
        float v = projb[a];
        const float* pp = projP + b * 1024 + a;
        for (int z = 0; z < Zp; z++) v += pp[(size_t)z * ssP];
        sP[a] = v;
    }
    __syncthreads();
    const float* att = att1 + (size_t)b * Pz * 1024;
    for (int p = warp; p < Pz; p += 16) {
        const float* ap = att + p * 1024;
        float part = 0.f;
#pragma unroll 4
        for (int a = lane; a < 1024; a += 32)
            part = fmaf(fmaxf(ap[a] + sP[a], 0.f), sW[a], part);
        for (int o = 16; o; o >>= 1) part += __shfl_down_sync(0xffffffffu, part, o);
        if (lane == 0) sScore[p] = part;
    }
    __syncthreads();
    if (tid == 0) {
        float mx = sScore[0];
        for (int p = 1; p < Pz; p++) mx = fmaxf(mx, sScore[p]);
        float sum = 0.f;
        for (int p = 0; p < Pz; p++) { float e = expf(sScore[p] - mx); sAlpha[p] = e; sum += e; }
        float inv = 1.f / sum;
        for (int p = 0; p < Pz; p++) sAlpha[p] *= inv;
    }
    __syncthreads();
    bool act = t < declen[b];
    if (tid < Pz) o_alpha[((size_t)b * Tz + t) * Pz + tid] = act ? sAlpha[tid] : 0.f;
    const float* ifb = IF + (size_t)b * Pz * Fz;
    for (int f = tid; f < Fz; f += 512) {
        float sv = 0.f;
#pragma unroll
        for (int p = 0; p < Pz; p++) sv = fmaf(sAlpha[p], ifb[p * Fz + f], sv);
        split2(sv, aweh + b * Fz + f, awel + b * Fz + f);
    }
}

// ---------- launch ----------
extern "C" void kernel_launch(void* const* d_in, const int* in_sizes, int n_in,
                              void* d_out, int out_size)
{
    const float* img_att = (const float*)d_in[0];
    const float* img_fc  = (const float*)d_in[1];
    const int*   enc     = (const int*)d_in[2];
    const int*   caplen  = (const int*)d_in[3];
    const float* emb     = (const float*)d_in[4];
    const float* Wfa     = (const float*)d_in[5];
    const float* bfa     = (const float*)d_in[6];
    const float* Wd1     = (const float*)d_in[7];
    const float* bd1     = (const float*)d_in[8];
    const float* Wd2     = (const float*)d_in[9];
    const float* bd2     = (const float*)d_in[10];
    const float* Wfull   = (const float*)d_in[11];
    const float* Wlang   = (const float*)d_in[13];
    const float* blang   = (const float*)d_in[14];
    const float* Watt    = (const float*)d_in[15];
    const float* batt    = (const float*)d_in[16];
    const float* Wout    = (const float*)d_in[17];
    const float* bout    = (const float*)d_in[18];
    const float* Wll_ih  = (const float*)d_in[19];
    const float* Wll_hh  = (const float*)d_in[20];
    const float* bll     = (const float*)d_in[21];
    const float* Wal_ih  = (const float*)d_in[22];
    const float* Wal_hh  = (const float*)d_in[23];
    const float* bal     = (const float*)d_in[24];
    const float* Wfc     = (const float*)d_in[25];
    const float* bfc     = (const float*)d_in[26];

    void* pf; cudaGetSymbolAddress(&pf, g_fs);
    void* ph; cudaGetSymbolAddress(&ph, g_hb);
    void* pi; cudaGetSymbolAddress(&pi, g_is);
    float* fs = (float*)pf;
    bf*    hb = (bf*)ph;
    int*   is = (int*)pi;
    cudaFuncSetAttribute(gemm_ms, cudaFuncAttributeMaxDynamicSharedMemorySize, GSM);

    static cudaStream_t s1 = nullptr, s2 = nullptr;
    static cudaEvent_t evS, evF, evA, evE;
    static cudaEvent_t evL[2], evP[2], evL2[2], evHd[2], evFl[2], evO[2];
    if (!s1) {
        cudaStreamCreateWithFlags(&s1, cudaStreamNonBlocking);
        cudaStreamCreateWithFlags(&s2, cudaStreamNonBlocking);
        cudaEventCreateWithFlags(&evS, cudaEventDisableTiming);
        cudaEventCreateWithFlags(&evF, cudaEventDisableTiming);
        cudaEventCreateWithFlags(&evA, cudaEventDisableTiming);
        cudaEventCreateWithFlags(&evE, cudaEventDisableTiming);
        for (int i = 0; i < 2; i++) {
            cudaEventCreateWithFlags(&evL[i], cudaEventDisableTiming);
            cudaEventCreateWithFlags(&evP[i], cudaEventDisableTiming);
            cudaEventCreateWithFlags(&evL2[i], cudaEventDisableTiming);
            cudaEventCreateWithFlags(&evHd[i], cudaEventDisableTiming);
            cudaEventCreateWithFlags(&evFl[i], cudaEventDisableTiming);
            cudaEventCreateWithFlags(&evO[i], cudaEventDisableTiming);
        }
    }

    float* IF    = fs + FS_IF;
    float* imgfc = fs + FS_IMGFC;
    float* att1  = fs + FS_ATT1;
    float* Eall  = fs + FS_EALL;
    float* gfc   = fs + FS_GFC;
    float* c1    = fs + FS_C1;
    float* c2    = fs + FS_C2;
    float* projb = fs + FS_PROJB;
    float* hidb  = fs + FS_HIDB;
    float* part  = fs + FS_PART;
    float* partB = fs + FS_PARTB;
    int* sortp = is, *declenp = is + 128, *capsp = is + 256;

    float* o_pred  = (float*)d_out;
    float* o_pred1 = o_pred + (size_t)Bz * Tz * Vz;
    float* o_caps  = o_pred1 + (size_t)Bz * Tz * Vz;
    float* o_dlen  = o_caps + Bz * Lz;
    float* o_alpha = o_dlen + Bz;
    float* o_sort  = o_alpha + (size_t)Bz * Tz * Pz;

    cudaEventRecord(evS, 0);
    cudaStreamWaitEvent(s1, evS, 0);
    cudaStreamWaitEvent(s2, evS, 0);

#define CVTS(st, src, ls, srcR, R, C, base) \
    convert_split<<<((size_t)(R)*(C) + 255) / 256, 256, 0, st>>>(src, ls, srcR, (R)*(C), C, hb + (base), hb + (base) + (size_t)(R)*(C))
    CVTS(s1, Wfc,  1024, 10000, 10240, 1024, HB_WFCP);
    CVTS(s2, Wout, 1024, 10000, 10240, 1024, HB_WOUTP);

    sort_kernel<<<1, 128>>>(caplen, enc, sortp, declenp, capsp, o_caps, o_dlen, o_sort);
    gather_kernel<<<Bz * Pz, 256>>>(img_att, img_fc, sortp, IF, imgfc);
    gather_emb<<<Tz * Bz, 256>>>(emb, capsp, hb + HB_EMBG, hb + HB_EMBG + 2490368);
    zero_init<<<1024, 256>>>(c1, c2, hb + HB_H1, hb + HB_H2);
    make_bias<<<4, 256>>>(bd1, bd2, blang, batt, projb, hidb);
    CVTS((cudaStream_t)0, Wfa, 2048, 1024, 1024, 2048, HB_WFA);
    CVTS((cudaStream_t)0, Wll_ih + 0,    4096, 4096, 4096, 1024, HB_WE);
    CVTS((cudaStream_t)0, Wll_ih + 1024, 4096, 4096, 4096, 1024, HB_WH);
    CVTS((cudaStream_t)0, Wll_ih + 2048, 4096, 4096, 4096, 2048, HB_WF);
    CVTS((cudaStream_t)0, Wll_hh, 1024, 4096, 4096, 1024, HB_WHH);
    CVTS((cudaStream_t)0, Wal_ih, 2048, 4096, 4096, 2048, HB_WALI);
    CVTS((cudaStream_t)0, Wal_hh, 1024, 4096, 4096, 1024, HB_WALH);
    CVTS((cudaStream_t)0, Wd1, 1024, 1024, 1024, 1024, HB_WD1);
    CVTS((cudaStream_t)0, Wd2, 1024, 1024, 1024, 1024, HB_WD2);
    CVTS((cudaStream_t)0, Wlang, 1024, 512, 512, 1024, HB_WLANG);
    CVTS((cudaStream_t)0, Watt,  1024, 512, 512, 1024, HB_WATT);
    CVTS((cudaStream_t)0, IF, 2048, 4736, 4736, 2048, HB_IF);
    CVTS((cudaStream_t)0, imgfc, 2048, 128, 128, 2048, HB_IMGFC);
#undef CVTS
    cudaEventRecord(evF, 0);
    cudaStreamWaitEvent(s1, evF, 0);
    cudaStreamWaitEvent(s2, evF, 0);

    auto setJ = [](GA& g, int job, int pass, const bf* ah, const bf* al,
                   const bf* wh, const bf* wl, int K) {
        g.p[job][pass][0] = ah; g.p[job][pass][1] = al;
        g.p[job][pass][2] = wh; g.p[job][pass][3] = wl;
        g.K[job][pass] = K;
    };
#define HP(o, n) hb + (o), hb + (o) + (n)

    // Eall = embg@We^T (s1)
    {
        GA g = {};
        setJ(g, 0, 0, HP(HB_EMBG, 2490368), HP(HB_WE, 4194304), 1024);
        g.NT1 = 32; g.S = 1; g.outF = Eall; g.ldo = 4096; g.Nvalid = 4096;
        gemm_ms<<<dim3(32, 19, 1), 256, GSM, s1>>>(g);
        cudaEventRecord(evE, s1);
    }
    // att1 = IF@Wfa^T + bfa (s2)
    {
        GA g = {};
        setJ(g, 0, 0, HP(HB_IF, 9699328), HP(HB_WFA, 2097152), 2048);
        g.NT1 = 8; g.S = 1; g.bias = bfa; g.outF = att1; g.ldo = 1024; g.Nvalid = 1024;
        gemm_ms<<<dim3(8, 37, 1), 256, GSM, s2>>>(g);
        cudaEventRecord(evA, s2);
    }
    // gfc = imgfc@Wf^T (stream 0)
    {
        GA g = {};
        setJ(g, 0, 0, HP(HB_IMGFC, 262144), HP(HB_WF, 8388608), 2048);
        g.NT1 = 32; g.S = 1; g.outF = gfc; g.ldo = 4096; g.Nvalid = 4096;
        gemm_ms<<<dim3(32, 1, 1), 256, GSM>>>(g);
    }
    cudaStreamWaitEvent(0, evE, 0);
    cudaStreamWaitEvent(0, evA, 0);

    const size_t H1N_O[2] = {HB_H1N, HB_H1N2};
    const size_t H2N_O[2] = {HB_H2N, HB_H2N2};
    const size_t HID_O[2] = {HB_HID, HB_HID2};

    for (int t = 0; t < Tz; t++) {
        int pb = t & 1;
        // protect H1N[pb] (preds1/hid readers) and H2N[pb] (hid reader)
        if (t >= 2) { cudaStreamWaitEvent(0, evP[pb], 0); cudaStreamWaitEvent(0, evHd[pb], 0); }
        // gates1 = h2@WH + h1@WHH, S=4 (skip at t=0: h1=h2=0)
        if (t > 0) {
            GA g = {};
            setJ(g, 0, 0, HP(HB_H2, 131072), HP(HB_WH, 4194304), 1024);
            setJ(g, 0, 1, HP(HB_H1, 131072), HP(HB_WHH, 4194304), 1024);
            g.NT1 = 32; g.S = 4; g.partial = part; g.ldP = 4096; g.ss = 524288;
            gemm_ms<<<dim3(32, 1, 4), 256, GSM>>>(g);
        }
        finish_lstm<<<512, 256>>>(part, t > 0 ? 4 : 0, 524288, gfc,
                                  Eall + (size_t)t * 524288, bll,
                                  c1, HP(HB_H1, 131072), HP(H1N_O[pb], 131072), declenp, t);
        cudaEventRecord(evL[pb], 0);
        cudaStreamWaitEvent(s1, evL[pb], 0);
        // preds1 [s1]
        {
            GA g = {};
            setJ(g, 0, 0, HP(H1N_O[pb], 131072), HP(HB_WFCP, 10485760), 1024);
            g.NT1 = 80; g.S = 1; g.bias = bfc; g.declen = declenp; g.t = t;
            g.outF = o_pred1 + (size_t)t * Vz; g.ldo = (long long)Tz * Vz; g.Nvalid = Vz;
            gemm_ms<<<dim3(80, 1, 1), 256, GSM, s1>>>(g);
            cudaEventRecord(evP[pb], s1);
        }
        // proj = h1n@Wd1 (+ h2@Wd2 if t>0), S=8
        {
            GA g = {};
            setJ(g, 0, 0, HP(H1N_O[pb], 131072), HP(HB_WD1, 1048576), 1024);
            if (t > 0) setJ(g, 0, 1, HP(HB_H2, 131072), HP(HB_WD2, 1048576), 1024);
            g.NT1 = 8; g.S = 8; g.partial = part; g.ldP = 1024; g.ss = 131072;
            gemm_ms<<<dim3(8, 1, 8), 256, GSM>>>(g);
        }
        attention_kernel<<<Bz, 512>>>(att1, part, 8, 131072, projb, Wfull, IF,
                                      hb + HB_AWE, hb + HB_AWE + 262144, o_alpha, declenp, t);
        // gates2 = awe@WALI (+ h2@WALH if t>0), S=4
        {
            GA g = {};
            setJ(g, 0, 0, HP(HB_AWE, 262144), HP(HB_WALI, 8388608), 2048);
            if (t > 0) setJ(g, 0, 1, HP(HB_H2, 131072), HP(HB_WALH, 4194304), 1024);
            g.NT1 = 32; g.S = 4; g.partial = part; g.ldP = 4096; g.ss = 524288;
            gemm_ms<<<dim3(32, 1, 4), 256, GSM>>>(g);
        }
        finish_lstm<<<512, 256>>>(part, 4, 524288, nullptr, nullptr, bal,
                                  c2, HP(HB_H2, 131072), HP(H2N_O[pb], 131072), declenp, t);
        cudaEventRecord(evL2[pb], 0);
        // ---- hid chain on s2 (off critical path) ----
        cudaStreamWaitEvent(s2, evL2[pb], 0);
        if (t >= 2) cudaStreamWaitEvent(s2, evO[pb], 0);   // HID[pb] reader
        {
            GA g = {};
            setJ(g, 0, 0, HP(H1N_O[pb], 131072), HP(HB_WLANG, 524288), 1024);
            setJ(g, 1, 0, HP(H2N_O[pb], 131072),
                 hb + HB_WATT - 524288, hb + HB_WATT, 1024);
            g.NT1 = 4; g.n01 = 0; g.n02 = 512; g.S = 8;
            g.partial = partB; g.ldP = 1024; g.ss = 131072;
            gemm_ms<<<dim3(8, 1, 8), 256, GSM, s2>>>(g);
            cudaEventRecord(evHd[pb], s2);
        }
        finish_linear<<<512, 256, 0, s2>>>(partB, 8, 131072, 1024, hidb, 1, nullptr, 0,
                                           hb + HID_O[pb], hb + HID_O[pb] + 131072, 128, 1024);
        cudaEventRecord(evFl[pb], s2);
        cudaStreamWaitEvent(s1, evFl[pb], 0);
        // out [s1]
        {
            GA g = {};
            setJ(g, 0, 0, HP(HID_O[pb], 131072), HP(HB_WOUTP, 10485760), 1024);
            g.NT1 = 80; g.S = 1; g.bias = bout; g.declen = declenp; g.t = t;
            g.outF = o_pred + (size_t)t * Vz; g.ldo = (long long)Tz * Vz; g.Nvalid = Vz;
            gemm_ms<<<dim3(80, 1, 1), 256, GSM, s1>>>(g);
            cudaEventRecord(evO[pb], s1);
        }
    }
    cudaStreamWaitEvent(0, evO[0], 0);
    cudaStreamWaitEvent(0, evO[1], 0);
#undef HP
}

// round 16
// speedup vs baseline: 8.1445x; 1.0244x over previous
#include <cuda_runtime.h>
#include <cuda_fp16.h>
#include <cstdint>

typedef __half hf;
#define Bz 128
#define Pz 37
#define Fz 2048
#define Vz 10000
#define Lz 20
#define Tz 19

#define TILEA 5120
#define TILEW 10240
#define BUF   30720
#define GSM   61440

__device__ __forceinline__ uint32_t smem_u32(const void* p) {
    uint32_t a;
    asm("{ .reg .u64 t; cvta.to.shared.u64 t, %1; cvt.u32.u64 %0, t; }" : "=r"(a) : "l"(p));
    return a;
}

#define LDMX4(R, addr) \
    asm volatile("ldmatrix.sync.aligned.m8n8.x4.shared.b16 {%0,%1,%2,%3}, [%4];" \
        : "=r"((R)[0]), "=r"((R)[1]), "=r"((R)[2]), "=r"((R)[3]) : "r"(addr))

#define MMA(C, A, B) \
    asm volatile("mma.sync.aligned.m16n8k16.row.col.f32.f16.f16.f32 " \
        "{%0,%1,%2,%3},{%4,%5,%6,%7},{%8,%9},{%0,%1,%2,%3};" \
        : "+f"((C)[0]), "+f"((C)[1]), "+f"((C)[2]), "+f"((C)[3]) \
        : "r"((A)[0]), "r"((A)[1]), "r"((A)[2]), "r"((A)[3]), "r"((B)[0]), "r"((B)[1]))

#define CPA(d, g) \
    asm volatile("cp.async.cg.shared.global [%0], [%1], 16;" :: "r"(d), "l"(g))

// ---------- static device memory ----------
__device__ float g_fs[28966912];
__device__ hf    g_hb[147062784];
__device__ int   g_is[4096];

#define FS_IF     0
#define FS_IMGFC  9699328
#define FS_ATT1   9961472
#define FS_EALL   14811136
#define FS_GFC    24772608
#define FS_C1     25427968
#define FS_C2     25559040
#define FS_PROJB  25690112
#define FS_HIDB   25691136
#define FS_PART   25692160
#define FS_PARTB  27789312

#define HB_WFA    0
#define HB_WE     4194304
#define HB_WH     12582912
#define HB_WF     20971520
#define HB_WHH    37748736
#define HB_WALI   46137344
#define HB_WALH   62914560
#define HB_WD1    71303168
#define HB_WD2    73400320
#define HB_WLANG  75497472
#define HB_WATT   76546048
#define HB_WFCP   77594624
#define HB_WOUTP  98566144
#define HB_IF     119537664
#define HB_IMGFC  138936320
#define HB_EMBG   139460608
#define HB_H1     144441344
#define HB_H2     144703488
#define HB_H1N    144965632
#define HB_H2N    145227776
#define HB_AWE    145489920
#define HB_HID    146014208
#define HB_H1N2   146276352
#define HB_HID2   146538496
#define HB_H2N2   146800640

__device__ __forceinline__ void split2(float v, hf* dh, hf* dl) {
    hf h = __float2half(v);
    *dh = h;
    *dl = __float2half(v - __half2float(h));
}

// ---------- preprocessing ----------
__global__ void sort_kernel(const int* __restrict__ caplen, const int* __restrict__ enc,
                            int* sortp, int* declenp, int* nactp, int* capsp,
                            float* o_caps, float* o_dlen, float* o_sort)
{
    __shared__ int len[Bz], sdl[Bz];
    int i = threadIdx.x;
    len[i] = caplen[i];
    __syncthreads();
    int li = len[i], rank = 0;
    for (int j = 0; j < Bz; j++) {
        int lj = len[j];
        rank += (lj > li) || (lj == li && j < i);
    }
    sortp[rank] = i;
    __syncthreads();
    int src = sortp[i];
    int dl = len[src] - 1;
    declenp[i] = dl;
    sdl[i] = dl;
    o_dlen[i] = (float)dl;
    o_sort[i] = (float)src;
    for (int k = 0; k < Lz; k++) {
        int c = enc[src * Lz + k];
        capsp[i * Lz + k] = c;
        o_caps[i * Lz + k] = (float)c;
    }
    __syncthreads();
    if (i < Tz) {
        int c = 0;
        for (int j = 0; j < Bz; j++) c += (sdl[j] > i);
        nactp[i] = c;
    }
}

__global__ void gather_kernel(const float* __restrict__ img_att, const float* __restrict__ img_fc,
                              const int* __restrict__ sortp, float* IF, float* imgfc)
{
    int bp = blockIdx.x, b = bp / Pz, p = bp % Pz;
    int src = sortp[b];
    const float* s = (p < 36) ? (img_att + ((size_t)src * 36 + p) * Fz) : (img_fc + (size_t)src * Fz);
    float* d = IF + (size_t)bp * Fz;
    for (int f = threadIdx.x; f < Fz; f += blockDim.x) d[f] = s[f];
    if (p == 36) {
        float* d2 = imgfc + (size_t)b * Fz;
        for (int f = threadIdx.x; f < Fz; f += blockDim.x) d2[f] = s[f];
    }
}

__global__ void gather_emb(const float* __restrict__ emb, const int* __restrict__ caps,
                           hf* dh, hf* dl)
{
    int r = blockIdx.x, t = r >> 7, b = r & 127;
    const float* s = emb + (size_t)caps[b * Lz + t] * 1024;
    for (int c = threadIdx.x; c < 1024; c += blockDim.x)
        split2(s[c], dh + (size_t)r * 1024 + c, dl + (size_t)r * 1024 + c);
}

__global__ void convert_split(const float* __restrict__ src, int ls, int srcR, int n, int C,
                              hf* dh, hf* dl)
{
    int i = blockIdx.x * blockDim.x + threadIdx.x;
    if (i >= n) return;
    int r = i / C, c = i % C;
    float v = (r < srcR) ? src[(size_t)r * ls + c] : 0.f;
    split2(v, dh + i, dl + i);
}

__global__ void make_bias(const float* bd1, const float* bd2, const float* blang,
                          const float* batt, float* projb, float* hidb)
{
    int i = blockIdx.x * blockDim.x + threadIdx.x;
    if (i < 1024) {
        projb[i] = bd1[i] + bd2[i];
        hidb[i] = (i < 512) ? blang[i] : batt[i - 512];
    }
}

__global__ void zero_init(float* c1, float* c2, hf* h1, hf* h2)
{
    int i = blockIdx.x * blockDim.x + threadIdx.x;
    if (i < 262144) {
        h1[i] = __float2half(0.f);
        h2[i] = __float2half(0.f);
        if (i < 131072) { c1[i] = 0.f; c2[i] = 0.f; }
    }
}

// ---------- generic mma.sync GEMM (M-tile 64, fp16 hi/lo, 2 or 3 terms) ----------
struct GA {
    const hf* p[2][2][4];   // [job][pass][Ah,Al,Wh,Wl]
    int K[2][2];
    int NT1, n01, n02, S;
    float* partial; int ldP, ss;
    const float* bias;
    const int* declen; int t;
    float* outF; long long ldo; int Nvalid;
    int terms;              // 2 or 3
    const int* nactp;       // per-t active rows (sorted prefix), or null
};

__global__ void __launch_bounds__(256, 2) gemm_ms(GA g)
{
    extern __shared__ char smem[];
    const int bx = blockIdx.x;
    const int job = (bx < g.NT1) ? 0 : 1;
    const int n0 = job ? g.n02 + (bx - g.NT1) * 128 : g.n01 + bx * 128;
    const int m0 = blockIdx.y * 64;
    const int s = blockIdx.z;
    const int tid = threadIdx.x;

    if (g.nactp && m0 >= __ldg(g.nactp + g.t)) {
        // fully-inactive M-tile: leaf outputs must still be zero-filled
        if (g.S == 1 && g.outF) {
            for (int i = tid; i < 64 * 128; i += 256) {
                int r = m0 + (i >> 7), c = n0 + (i & 127);
                if (c < g.Nvalid) g.outF[(size_t)r * g.ldo + c] = 0.f;
            }
        }
        return;
    }

    const int K1g = g.K[job][0], K2g = g.K[job][1];
    const int Ks1 = K1g / g.S, Ks2 = K2g ? K2g / g.S : 0;
    const int NC1 = Ks1 >> 5, NCt = NC1 + (Ks2 >> 5);
    const uint32_t sbase = smem_u32(smem);

    // loader: 1536 16B-chunks (A tiles 64x32, W tiles 128x32, hi/lo) over 256 threads x 6
    int lenc[6]; uint32_t ldst[6];
#pragma unroll
    for (int it = 0; it < 6; it++) {
        int u = tid + it * 256;
        int tile, rel;
        if (u < 512) { tile = u >> 8; rel = u & 255; }
        else { tile = 2 + ((u - 512) >> 9); rel = (u - 512) & 511; }
        int row = rel >> 2, ck = rel & 3;
        int rg = ((tile < 2) ? m0 : n0) + row;
        lenc[it] = tile | (ck << 2) | (rg << 4);
        ldst[it] = (uint32_t)((tile == 0 ? 0 : tile == 1 ? TILEA : tile == 2 ? 2 * TILEA : 2 * TILEA + TILEW)
                   + row * 80 + ck * 16);
    }

    const int lane = tid & 31, warp = tid >> 5;
    const int wm = warp >> 2, wn = warp & 3;
    const int arow = (lane & 7) + ((lane >> 3) & 1) * 8;
    const uint32_t akoff = (uint32_t)((lane >> 4) * 16);
    const int brow = (lane & 7) + ((lane >> 4) << 3);
    const uint32_t bkoff = (uint32_t)(((lane >> 3) & 1) * 16);
    const uint32_t aoff = (uint32_t)((wm * 32 + arow) * 80) + akoff;
    const uint32_t boff = 2u * TILEA + (uint32_t)((wn * 32 + brow) * 80) + bkoff;
    const bool T3 = (g.terms == 3);

    float acc[2][4][4] = {};

#define LDCHUNK(bufi, PP, KK, kg) do { \
    const hf* const* _P = (PP); const int _K = (KK); const int _kg = (kg); \
    const uint32_t _bo = sbase + (bufi) * BUF; \
    _Pragma("unroll") \
    for (int i = 0; i < 6; i++) { \
        int e = lenc[i]; \
        const hf* gp = _P[e & 3] + (size_t)(e >> 4) * _K + _kg + ((e >> 2) & 3) * 8; \
        CPA(_bo + ldst[i], gp); \
    } \
} while (0)

    LDCHUNK(0, g.p[job][0], K1g, s * Ks1);
    asm volatile("cp.async.commit_group;" ::: "memory");

    for (int c = 0; c < NCt; c++) {
        if (c + 1 < NCt) {
            if (c + 1 < NC1) LDCHUNK((c + 1) & 1, g.p[job][0], K1g, s * Ks1 + (c + 1) * 32);
            else             LDCHUNK((c + 1) & 1, g.p[job][1], K2g, s * Ks2 + (c + 1 - NC1) * 32);
            asm volatile("cp.async.commit_group;" ::: "memory");
            asm volatile("cp.async.wait_group 1;" ::: "memory");
        } else {
            asm volatile("cp.async.wait_group 0;" ::: "memory");
        }
        __syncthreads();
        const uint32_t sc = sbase + (c & 1) * BUF;
#pragma unroll
        for (int kk = 0; kk < 2; kk++) {
            const uint32_t kb = kk * 32;
            uint32_t Bh[8], Bl[8];
#pragma unroll
            for (int p = 0; p < 2; p++) {
                LDMX4(&Bh[4 * p], sc + boff + p * 1280 + kb);
                LDMX4(&Bl[4 * p], sc + boff + TILEW + p * 1280 + kb);
            }
#pragma unroll
            for (int mt = 0; mt < 2; mt++) {
                uint32_t Af[4], Ag[4];
                LDMX4(Af, sc + aoff + mt * 1280 + kb);
                if (T3) LDMX4(Ag, sc + aoff + TILEA + mt * 1280 + kb);
#pragma unroll
                for (int nt = 0; nt < 4; nt++) {
                    MMA(acc[mt][nt], Af, &Bh[2 * nt]);
                    MMA(acc[mt][nt], Af, &Bl[2 * nt]);
                    if (T3) MMA(acc[mt][nt], Ag, &Bh[2 * nt]);
                }
            }
        }
        __syncthreads();
    }
#undef LDCHUNK

    const int rr = lane >> 2, cc = (lane & 3) * 2;
    if (g.S > 1) {
        float* op = g.partial + (size_t)s * g.ss;
#pragma unroll
        for (int mt = 0; mt < 2; mt++) {
            int row = m0 + wm * 32 + mt * 16 + rr;
#pragma unroll
            for (int nt = 0; nt < 4; nt++) {
                int col = n0 + wn * 32 + nt * 8 + cc;
                *(float2*)(op + (size_t)row * g.ldP + col) = make_float2(acc[mt][nt][0], acc[mt][nt][1]);
                *(float2*)(op + (size_t)(row + 8) * g.ldP + col) = make_float2(acc[mt][nt][2], acc[mt][nt][3]);
            }
        }
    } else {
#pragma unroll
        for (int mt = 0; mt < 2; mt++) {
            int row = m0 + wm * 32 + mt * 16 + rr;
            bool a0 = !g.declen || (g.t < g.declen[row]);
            bool a1 = !g.declen || (g.t < g.declen[row + 8]);
#pragma unroll
            for (int nt = 0; nt < 4; nt++) {
                int col = n0 + wn * 32 + nt * 8 + cc;
                if (col < g.Nvalid) {
                    float bb0 = g.bias ? g.bias[col] : 0.f;
                    float bb1 = g.bias ? g.bias[col + 1] : 0.f;
                    float v0 = acc[mt][nt][0] + bb0, v1 = acc[mt][nt][1] + bb1;
                    float v2 = acc[mt][nt][2] + bb0, v3 = acc[mt][nt][3] + bb1;
                    if (!a0) { v0 = 0.f; v1 = 0.f; }
                    if (!a1) { v2 = 0.f; v3 = 0.f; }
                    *(float2*)(g.outF + (size_t)row * g.ldo + col) = make_float2(v0, v1);
                    *(float2*)(g.outF + (size_t)(row + 8) * g.ldo + col) = make_float2(v2, v3);
                }
            }
        }
    }
}

// ---------- finish kernels ----------
__global__ void finish_linear(const float* __restrict__ P, int Z, int ss, int ldP,
                              const float* __restrict__ bias, int relu,
                              float* __restrict__ outF, int ldo,
                              hf* dh, hf* dl, int M, int N)
{
    int i = blockIdx.x * blockDim.x + threadIdx.x;
    if (i >= M * N) return;
    int m = i / N, n = i % N;
    float v = bias ? bias[n] : 0.f;
    const float* p = P + (size_t)m * ldP + n;
    for (int z = 0; z < Z; z++) v += p[(size_t)z * ss];
    if (relu) v = fmaxf(v, 0.f);
    if (outF) outF[(size_t)m * ldo + n] = v;
    if (dh) split2(v, dh + i, dl + i);
}

__global__ void finish_lstm(const float* __restrict__ P, int Z, int ss,
                            const float* __restrict__ addA, const float* __restrict__ addB,
                            const float* __restrict__ bias, float* __restrict__ cst,
                            hf* hh, hf* hl, hf* hnh, hf* hnl,
                            const int* __restrict__ declen, int t)
{
    int idx = blockIdx.x * blockDim.x + threadIdx.x;
    if (idx >= Bz * 1024) return;
    int b = idx >> 10, d = idx & 1023;
    float g4[4];
#pragma unroll
    for (int q = 0; q < 4; q++) {
        int n = d + q * 1024;
        float v = bias[n];
        if (addA) v += addA[b * 4096 + n];
        if (addB) v += addB[b * 4096 + n];
        for (int z = 0; z < Z; z++) v += P[(size_t)z * ss + b * 4096 + n];
        g4[q] = v;
    }
    float si = 1.f / (1.f + expf(-g4[0]));
    float sf = 1.f / (1.f + expf(-g4[1]));
    float so = 1.f / (1.f + expf(-g4[3]));
    float cn = sf * cst[idx] + si * tanhf(g4[2]);
    float hv = so * tanhf(cn);
    split2(hv, hnh + idx, hnl + idx);
    if (t < declen[b]) { cst[idx] = cn; split2(hv, hh + idx, hl + idx); }
}

// ---------- attention ----------
__global__ void __launch_bounds__(512)
attention_kernel(const float* __restrict__ att1, const float* __restrict__ projP,
                 int Zp, int ssP, const float* __restrict__ projb,
                 const float* __restrict__ Wfull, const float* __restrict__ IF,
                 hf* aweh, hf* awel, float* __restrict__ o_alpha,
                 const int* __restrict__ nactp, int t)
{
    int b = blockIdx.x, tid = threadIdx.x, lane = tid & 31, warp = tid >> 5;
    if (b >= __ldg(nactp + t)) {
        if (tid < Pz) o_alpha[((size_t)b * Tz + t) * Pz + tid] = 0.f;
        return;
    }
    __shared__ float sW[1024], sP[1024], sScore[Pz], sAlpha[Pz];
    for (int a = tid; a < 1024; a += 512) {
        sW[a] = Wfull[a];
        float v = projb[a];
        const float* pp = projP + b * 1024 + a;
        for (int z = 0; z < Zp; z++) v += pp[(size_t)z * ssP];
        sP[a] = v;
    }
    __syncthreads();
    const float* att = att1 + (size_t)b * Pz * 1024;
    for (int p = warp; p < Pz; p += 16) {
        const float* ap = att + p * 1024;
        float part = 0.f;
#pragma unroll 4
        for (int a = lane; a < 1024; a += 32)
            part = fmaf(fmaxf(ap[a] + sP[a], 0.f), sW[a], part);
        for (int o = 16; o; o >>= 1) part += __shfl_down_sync(0xffffffffu, part, o);
        if (lane == 0) sScore[p] = part;
    }
    __syncthreads();
    if (tid == 0) {
        float mx = sScore[0];
        for (int p = 1; p < Pz; p++) mx = fmaxf(mx, sScore[p]);
        float sum = 0.f;
        for (int p = 0; p < Pz; p++) { float e = expf(sScore[p] - mx); sAlpha[p] = e; sum += e; }
        float inv = 1.f / sum;
        for (int p = 0; p < Pz; p++) sAlpha[p] *= inv;
    }
    __syncthreads();
    if (tid < Pz) o_alpha[((size_t)b * Tz + t) * Pz + tid] = sAlpha[tid];
    const float* ifb = IF + (size_t)b * Pz * Fz;
    for (int f = tid; f < Fz; f += 512) {
        float sv = 0.f;
#pragma unroll
        for (int p = 0; p < Pz; p++) sv = fmaf(sAlpha[p], ifb[p * Fz + f], sv);
        split2(sv, aweh + b * Fz + f, awel + b * Fz + f);
    }
}

// ---------- launch ----------
extern "C" void kernel_launch(void* const* d_in, const int* in_sizes, int n_in,
                              void* d_out, int out_size)
{
    const float* img_att = (const float*)d_in[0];
    const float* img_fc  = (const float*)d_in[1];
    const int*   enc     = (const int*)d_in[2];
    const int*   caplen  = (const int*)d_in[3];
    const float* emb     = (const float*)d_in[4];
    const float* Wfa     = (const float*)d_in[5];
    const float* bfa     = (const float*)d_in[6];
    const float* Wd1     = (const float*)d_in[7];
    const float* bd1     = (const float*)d_in[8];
    const float* Wd2     = (const float*)d_in[9];
    const float* bd2     = (const float*)d_in[10];
    const float* Wfull   = (const float*)d_in[11];
    const float* Wlang   = (const float*)d_in[13];
    const float* blang   = (const float*)d_in[14];
    const float* Watt    = (const float*)d_in[15];
    const float* batt    = (const float*)d_in[16];
    const float* Wout    = (const float*)d_in[17];
    const float* bout    = (const float*)d_in[18];
    const float* Wll_ih  = (const float*)d_in[19];
    const float* Wll_hh  = (const float*)d_in[20];
    const float* bll     = (const float*)d_in[21];
    const float* Wal_ih  = (const float*)d_in[22];
    const float* Wal_hh  = (const float*)d_in[23];
    const float* bal     = (const float*)d_in[24];
    const float* Wfc     = (const float*)d_in[25];
    const float* bfc     = (const float*)d_in[26];

    void* pf; cudaGetSymbolAddress(&pf, g_fs);
    void* ph; cudaGetSymbolAddress(&ph, g_hb);
    void* pi; cudaGetSymbolAddress(&pi, g_is);
    float* fs = (float*)pf;
    hf*    hb = (hf*)ph;
    int*   is = (int*)pi;
    cudaFuncSetAttribute(gemm_ms, cudaFuncAttributeMaxDynamicSharedMemorySize, GSM);

    static cudaStream_t s1 = nullptr, s2 = nullptr;
    static cudaEvent_t evS, evF, evA, evE;
    static cudaEvent_t evL[2], evP[2], evL2[2], evHd[2], evFl[2], evO[2];
    if (!s1) {
        cudaStreamCreateWithFlags(&s1, cudaStreamNonBlocking);
        cudaStreamCreateWithFlags(&s2, cudaStreamNonBlocking);
        cudaEventCreateWithFlags(&evS, cudaEventDisableTiming);
        cudaEventCreateWithFlags(&evF, cudaEventDisableTiming);
        cudaEventCreateWithFlags(&evA, cudaEventDisableTiming);
        cudaEventCreateWithFlags(&evE, cudaEventDisableTiming);
        for (int i = 0; i < 2; i++) {
            cudaEventCreateWithFlags(&evL[i], cudaEventDisableTiming);
            cudaEventCreateWithFlags(&evP[i], cudaEventDisableTiming);
            cudaEventCreateWithFlags(&evL2[i], cudaEventDisableTiming);
            cudaEventCreateWithFlags(&evHd[i], cudaEventDisableTiming);
            cudaEventCreateWithFlags(&evFl[i], cudaEventDisableTiming);
            cudaEventCreateWithFlags(&evO[i], cudaEventDisableTiming);
        }
    }

    float* IF    = fs + FS_IF;
    float* imgfc = fs + FS_IMGFC;
    float* att1  = fs + FS_ATT1;
    float* Eall  = fs + FS_EALL;
    float* gfc   = fs + FS_GFC;
    float* c1    = fs + FS_C1;
    float* c2    = fs + FS_C2;
    float* projb = fs + FS_PROJB;
    float* hidb  = fs + FS_HIDB;
    float* part  = fs + FS_PART;
    float* partB = fs + FS_PARTB;
    int* sortp = is, *declenp = is + 128, *capsp = is + 256, *nactp = is + 2816;

    float* o_pred  = (float*)d_out;
    float* o_pred1 = o_pred + (size_t)Bz * Tz * Vz;
    float* o_caps  = o_pred1 + (size_t)Bz * Tz * Vz;
    float* o_dlen  = o_caps + Bz * Lz;
    float* o_alpha = o_dlen + Bz;
    float* o_sort  = o_alpha + (size_t)Bz * Tz * Pz;

    cudaEventRecord(evS, 0);
    cudaStreamWaitEvent(s1, evS, 0);
    cudaStreamWaitEvent(s2, evS, 0);

#define CVTS(st, src, ls, srcR, R, C, base) \
    convert_split<<<((size_t)(R)*(C) + 255) / 256, 256, 0, st>>>(src, ls, srcR, (R)*(C), C, hb + (base), hb + (base) + (size_t)(R)*(C))
    CVTS(s1, Wfc,  1024, 10000, 10240, 1024, HB_WFCP);
    CVTS(s2, Wout, 1024, 10000, 10240, 1024, HB_WOUTP);

    sort_kernel<<<1, 128>>>(caplen, enc, sortp, declenp, nactp, capsp, o_caps, o_dlen, o_sort);
    gather_kernel<<<Bz * Pz, 256>>>(img_att, img_fc, sortp, IF, imgfc);
    gather_emb<<<Tz * Bz, 256>>>(emb, capsp, hb + HB_EMBG, hb + HB_EMBG + 2490368);
    zero_init<<<1024, 256>>>(c1, c2, hb + HB_H1, hb + HB_H2);
    make_bias<<<4, 256>>>(bd1, bd2, blang, batt, projb, hidb);
    CVTS((cudaStream_t)0, Wfa, 2048, 1024, 1024, 2048, HB_WFA);
    CVTS((cudaStream_t)0, Wll_ih + 0,    4096, 4096, 4096, 1024, HB_WE);
    CVTS((cudaStream_t)0, Wll_ih + 1024, 4096, 4096, 4096, 1024, HB_WH);
    CVTS((cudaStream_t)0, Wll_ih + 2048, 4096, 4096, 4096, 2048, HB_WF);
    CVTS((cudaStream_t)0, Wll_hh, 1024, 4096, 4096, 1024, HB_WHH);
    CVTS((cudaStream_t)0, Wal_ih, 2048, 4096, 4096, 2048, HB_WALI);
    CVTS((cudaStream_t)0, Wal_hh, 1024, 4096, 4096, 1024, HB_WALH);
    CVTS((cudaStream_t)0, Wd1, 1024, 1024, 1024, 1024, HB_WD1);
    CVTS((cudaStream_t)0, Wd2, 1024, 1024, 1024, 1024, HB_WD2);
    CVTS((cudaStream_t)0, Wlang, 1024, 512, 512, 1024, HB_WLANG);
    CVTS((cudaStream_t)0, Watt,  1024, 512, 512, 1024, HB_WATT);
    CVTS((cudaStream_t)0, IF, 2048, 4736, 4736, 2048, HB_IF);
    CVTS((cudaStream_t)0, imgfc, 2048, 128, 128, 2048, HB_IMGFC);
#undef CVTS
    cudaEventRecord(evF, 0);
    cudaStreamWaitEvent(s1, evF, 0);
    cudaStreamWaitEvent(s2, evF, 0);

    auto setJ = [](GA& g, int job, int pass, const hf* ah, const hf* al,
                   const hf* wh, const hf* wl, int K) {
        g.p[job][pass][0] = ah; g.p[job][pass][1] = al;
        g.p[job][pass][2] = wh; g.p[job][pass][3] = wl;
        g.K[job][pass] = K;
    };
#define HP(o, n) hb + (o), hb + (o) + (n)

    // Eall = embg@We^T (s1), M=2432 -> 38 M-tiles
    {
        GA g = {};
        setJ(g, 0, 0, HP(HB_EMBG, 2490368), HP(HB_WE, 4194304), 1024);
        g.NT1 = 32; g.S = 1; g.outF = Eall; g.ldo = 4096; g.Nvalid = 4096; g.terms = 3;
        gemm_ms<<<dim3(32, 38, 1), 256, GSM, s1>>>(g);
        cudaEventRecord(evE, s1);
    }
    // att1 = IF@Wfa^T + bfa (s2), M=4736 -> 74 M-tiles
    {
        GA g = {};
        setJ(g, 0, 0, HP(HB_IF, 9699328), HP(HB_WFA, 2097152), 2048);
        g.NT1 = 8; g.S = 1; g.bias = bfa; g.outF = att1; g.ldo = 1024; g.Nvalid = 1024; g.terms = 3;
        gemm_ms<<<dim3(8, 74, 1), 256, GSM, s2>>>(g);
        cudaEventRecord(evA, s2);
    }
    // gfc = imgfc@Wf^T (stream 0)
    {
        GA g = {};
        setJ(g, 0, 0, HP(HB_IMGFC, 262144), HP(HB_WF, 8388608), 2048);
        g.NT1 = 32; g.S = 1; g.outF = gfc; g.ldo = 4096; g.Nvalid = 4096; g.terms = 3;
        gemm_ms<<<dim3(32, 2, 1), 256, GSM>>>(g);
    }
    cudaStreamWaitEvent(0, evE, 0);
    cudaStreamWaitEvent(0, evA, 0);

    const size_t H1N_O[2] = {HB_H1N, HB_H1N2};
    const size_t H2N_O[2] = {HB_H2N, HB_H2N2};
    const size_t HID_O[2] = {HB_HID, HB_HID2};

    for (int t = 0; t < Tz; t++) {
        int pb = t & 1;
        if (t >= 2) { cudaStreamWaitEvent(0, evP[pb], 0); cudaStreamWaitEvent(0, evHd[pb], 0); }
        // gates1 = h2@WH + h1@WHH, S=2
        if (t > 0) {
            GA g = {};
            setJ(g, 0, 0, HP(HB_H2, 131072), HP(HB_WH, 4194304), 1024);
            setJ(g, 0, 1, HP(HB_H1, 131072), HP(HB_WHH, 4194304), 1024);
            g.NT1 = 32; g.S = 2; g.partial = part; g.ldP = 4096; g.ss = 524288;
            g.terms = 3; g.nactp = nactp; g.t = t;
            gemm_ms<<<dim3(32, 2, 2), 256, GSM>>>(g);
        }
        finish_lstm<<<512, 256>>>(part, t > 0 ? 2 : 0, 524288, gfc,
                                  Eall + (size_t)t * 524288, bll,
                                  c1, HP(HB_H1, 131072), HP(H1N_O[pb], 131072), declenp, t);
        cudaEventRecord(evL[pb], 0);
        cudaStreamWaitEvent(s1, evL[pb], 0);
        // preds1 = h1n@Wfc^T (2-term fp16 leaf) [s1]
        {
            GA g = {};
            setJ(g, 0, 0, HP(H1N_O[pb], 131072), HP(HB_WFCP, 10485760), 1024);
            g.NT1 = 80; g.S = 1; g.bias = bfc; g.declen = declenp; g.t = t;
            g.outF = o_pred1 + (size_t)t * Vz; g.ldo = (long long)Tz * Vz; g.Nvalid = Vz;
            g.terms = 2; g.nactp = nactp;
            gemm_ms<<<dim3(80, 2, 1), 256, GSM, s1>>>(g);
            cudaEventRecord(evP[pb], s1);
        }
        // proj = h1n@Wd1 (+ h2@Wd2), S=4
        {
            GA g = {};
            setJ(g, 0, 0, HP(H1N_O[pb], 131072), HP(HB_WD1, 1048576), 1024);
            if (t > 0) setJ(g, 0, 1, HP(HB_H2, 131072), HP(HB_WD2, 1048576), 1024);
            g.NT1 = 8; g.S = 4; g.partial = part; g.ldP = 1024; g.ss = 131072;
            g.terms = 3; g.nactp = nactp; g.t = t;
            gemm_ms<<<dim3(8, 2, 4), 256, GSM>>>(g);
        }
        attention_kernel<<<Bz, 512>>>(att1, part, 4, 131072, projb, Wfull, IF,
                                      hb + HB_AWE, hb + HB_AWE + 262144, o_alpha, nactp, t);
        // gates2 = awe@WALI (+ h2@WALH), S=2
        {
            GA g = {};
            setJ(g, 0, 0, HP(HB_AWE, 262144), HP(HB_WALI, 8388608), 2048);
            if (t > 0) setJ(g, 0, 1, HP(HB_H2, 131072), HP(HB_WALH, 4194304), 1024);
            g.NT1 = 32; g.S = 2; g.partial = part; g.ldP = 4096; g.ss = 524288;
            g.terms = 3; g.nactp = nactp; g.t = t;
            gemm_ms<<<dim3(32, 2, 2), 256, GSM>>>(g);
        }
        finish_lstm<<<512, 256>>>(part, 2, 524288, nullptr, nullptr, bal,
                                  c2, HP(HB_H2, 131072), HP(H2N_O[pb], 131072), declenp, t);
        cudaEventRecord(evL2[pb], 0);
        // ---- hid chain on s2 ----
        cudaStreamWaitEvent(s2, evL2[pb], 0);
        if (t >= 2) cudaStreamWaitEvent(s2, evO[pb], 0);
        {
            GA g = {};
            setJ(g, 0, 0, HP(H1N_O[pb], 131072), HP(HB_WLANG, 524288), 1024);
            setJ(g, 1, 0, HP(H2N_O[pb], 131072),
                 hb + HB_WATT - 524288, hb + HB_WATT, 1024);
            g.NT1 = 4; g.n01 = 0; g.n02 = 512; g.S = 4;
            g.partial = partB; g.ldP = 1024; g.ss = 131072;
            g.terms = 3; g.nactp = nactp; g.t = t;
            gemm_ms<<<dim3(8, 2, 4), 256, GSM, s2>>>(g);
            cudaEventRecord(evHd[pb], s2);
        }
        finish_linear<<<512, 256, 0, s2>>>(partB, 4, 131072, 1024, hidb, 1, nullptr, 0,
                                           hb + HID_O[pb], hb + HID_O[pb] + 131072, 128, 1024);
        cudaEventRecord(evFl[pb], s2);
        cudaStreamWaitEvent(s1, evFl[pb], 0);
        // out = hid@Wout^T (2-term fp16 leaf) [s1]
        {
            GA g = {};
            setJ(g, 0, 0, HP(HID_O[pb], 131072), HP(HB_WOUTP, 10485760), 1024);
            g.NT1 = 80; g.S = 1; g.bias = bout; g.declen = declenp; g.t = t;
            g.outF = o_pred + (size_t)t * Vz; g.ldo = (long long)Tz * Vz; g.Nvalid = Vz;
            g.terms = 2; g.nactp = nactp;
            gemm_ms<<<dim3(80, 2, 1), 256, GSM, s1>>>(g);
            cudaEventRecord(evO[pb], s1);
        }
    }
    cudaStreamWaitEvent(0, evO[0], 0);
    cudaStreamWaitEvent(0, evO[1], 0);
#undef HP
}